// round 5
// baseline (speedup 1.0000x reference)
#include <cuda_runtime.h>

// ---------------------------------------------------------------------------
// Fused LSTMMeasurementPredictor — round 5
//   B=131072, H=128, NQ=2, P=32, D_IN=17, T=16
// 1024 threads / 64-batch tile (occ 50%). FFMA2 batch-pair accumulators with
// DUPLICATED-PAIR weights (zero dup-movs in inner loop), distance-1 weight
// prefetch, HC ping-pong. Thread GEMM tile: 4 gate-cols x 8 batches.
// ---------------------------------------------------------------------------

#define NTH 1024
#define BT  64
#define SS  68   // padded row stride (floats) for [K][64] smem buffers

constexpr int OFF_X   = 0;                   // 17  rows : x
constexpr int OFF_HCA = OFF_X   + 17  * SS;  // 128 rows : cell h (ping)
constexpr int OFF_HCB = OFF_HCA + 128 * SS;  // 128 rows : cell h (pong) / s staging
constexpr int OFF_CC  = OFF_HCB + 128 * SS;  // 128 rows : cell c
constexpr int OFF_H0  = OFF_CC  + 128 * SS;  // 32  rows : lstm0 proj h
constexpr int OFF_C0  = OFF_H0  + 32  * SS;  // 128 rows : lstm0 c
constexpr int OFF_H1  = OFF_C0  + 128 * SS;  // 32  rows : lstm1 proj h
constexpr int OFF_C1  = OFF_H1  + 32  * SS;  // 128 rows : lstm1 c
constexpr int OFF_RHO = OFF_C1  + 128 * SS;  // 64*33    : rho
constexpr int OFF_V   = OFF_RHO + 64 * 33;   // 8 rows   : projector v
constexpr int SMEM_FLOATS = OFF_V + 8 * SS;
constexpr int SMEM_BYTES  = SMEM_FLOATS * 4; // ~202 KB

// Duplicated-pair packed weights: Wd[k][1024], Wd[k][2j]=Wd[k][2j+1]=W[k][j],
// column j = u*4 + gate (i,f,g,o). +2048 pad floats for prefetch overshoot.
__device__ __align__(16) float g_Wc[145 * 1024 + 2048];
__device__ __align__(16) float g_bc[1024];
__device__ __align__(16) float g_W0[49 * 1024 + 2048];
__device__ __align__(16) float g_b0[1024];
__device__ __align__(16) float g_W1[64 * 1024 + 2048];
__device__ __align__(16) float g_b1[1024];
// dup'd proj weights: [k][64] with [2n]=[2n+1]=WhrT[k][n]
__device__ __align__(16) float g_Whr0T[128 * 64];
__device__ __align__(16) float g_Whr1T[128 * 64];
// dup'd Wp: [k][16]
__device__ __align__(16) float g_WpT[128 * 16];
__device__ __align__(16) float g_bpd[16];

__global__ void prep_kernel(
    const float* __restrict__ Wihc, const float* __restrict__ Whhc,
    const float* __restrict__ bihc, const float* __restrict__ bhhc,
    const float* __restrict__ Wp,   const float* __restrict__ bp,
    const float* __restrict__ Wih0, const float* __restrict__ Whh0,
    const float* __restrict__ bih0, const float* __restrict__ bhh0,
    const float* __restrict__ Whr0,
    const float* __restrict__ Wih1, const float* __restrict__ Whh1,
    const float* __restrict__ bih1, const float* __restrict__ bhh1,
    const float* __restrict__ Whr1)
{
    int i0 = blockIdx.x * blockDim.x + threadIdx.x;
    int stride = gridDim.x * blockDim.x;

    for (int i = i0; i < 145 * 1024; i += stride) {
        int k = i >> 10, jp = (i & 1023) >> 1;
        int u = jp >> 2, g = jp & 3, j = g * 128 + u;
        g_Wc[i] = (k < 17) ? Wihc[j * 17 + k] : Whhc[j * 128 + (k - 17)];
    }
    for (int i = i0; i < 49 * 1024; i += stride) {
        int k = i >> 10, jp = (i & 1023) >> 1;
        int u = jp >> 2, g = jp & 3, j = g * 128 + u;
        g_W0[i] = (k < 17) ? Wih0[j * 17 + k] : Whh0[j * 32 + (k - 17)];
    }
    for (int i = i0; i < 64 * 1024; i += stride) {
        int k = i >> 10, jp = (i & 1023) >> 1;
        int u = jp >> 2, g = jp & 3, j = g * 128 + u;
        g_W1[i] = (k < 32) ? Wih1[j * 32 + k] : Whh1[j * 32 + (k - 32)];
    }
    for (int i = i0; i < 2048; i += stride) {
        g_Wc[145 * 1024 + i] = 0.f;
        g_W0[49 * 1024 + i] = 0.f;
        g_W1[64 * 1024 + i] = 0.f;
    }
    for (int i = i0; i < 1024; i += stride) {
        int jp = i >> 1;
        int u = jp >> 2, g = jp & 3, j = g * 128 + u;
        g_bc[i] = bihc[j] + bhhc[j];
        g_b0[i] = bih0[j] + bhh0[j];
        g_b1[i] = bih1[j] + bhh1[j];
    }
    for (int i = i0; i < 128 * 64; i += stride) {
        int k = i >> 6, n = (i & 63) >> 1;
        g_Whr0T[i] = Whr0[n * 128 + k];
        g_Whr1T[i] = Whr1[n * 128 + k];
    }
    for (int i = i0; i < 128 * 16; i += stride) {
        int k = i >> 4, n = (i & 15) >> 1;
        g_WpT[i] = Wp[n * 128 + k];
    }
    for (int i = i0; i < 16; i += stride)
        g_bpd[i] = bp[i >> 1];
}

// ---------------------------------------------------------------------------
typedef unsigned long long ull;

__device__ __forceinline__ void fma2(ull& acc, ull a, ull b) {
    asm("fma.rn.f32x2 %0, %1, %2, %0;" : "+l"(acc) : "l"(a), "l"(b));
}
__device__ __forceinline__ void unpk(ull v, float& lo, float& hi) {
    asm("mov.b64 {%0, %1}, %2;" : "=f"(lo), "=f"(hi) : "l"(v));
}

__device__ __forceinline__ float fsig(float x) {
    return __fdividef(1.0f, 1.0f + __expf(-x));
}
__device__ __forceinline__ float ftanh(float x) {
    return __fdividef(2.0f, 1.0f + __expf(-2.0f * x)) - 1.0f;
}

// LSTM step: G[64,512] = [A(KA); B(KB)] @ W + bias, then gate update.
// Thread: unit u = tid&127 (gate cols 4u..4u+3), batches b0=(tid>>7)*8 ..+7.
// acc[gate][pair], pair = batches (b0+2p, b0+2p+1).
// Weights duplicated-pair: per k one 32B chunk (2x LDG.128) = 4 dup'd cols.
// NO internal barrier: {shC, shOut} elementwise-owned, disjoint from reads.
template <int KA, int KB>
__device__ __forceinline__ void lstm_step(
    const float* __restrict__ W, const float* __restrict__ bias,
    const float* shA, const float* shB, float* shC, float* shOut,
    int u, int b0)
{
    constexpr int K = KA + KB;
    ull acc[4][4];
    {
        ulonglong2 bA = *(const ulonglong2*)(bias + 8 * u);
        ulonglong2 bB = *(const ulonglong2*)(bias + 8 * u + 4);
#pragma unroll
        for (int p = 0; p < 4; ++p) {
            acc[0][p] = bA.x; acc[1][p] = bA.y;
            acc[2][p] = bB.x; acc[3][p] = bB.y;
        }
    }
    const float* Wu    = W + 8 * u;
    const float* baseA = shA + b0;
    const float* baseB = shB + b0 - KA * SS;

    ulonglong2 w0 = __ldg((const ulonglong2*)(Wu));
    ulonglong2 w1 = __ldg((const ulonglong2*)(Wu + 4));
#pragma unroll 2
    for (int k = 0; k < K; ++k) {
        const float* wn = Wu + (k + 1) * 1024;           // pad-safe overshoot
        ulonglong2 n0 = __ldg((const ulonglong2*)(wn));
        ulonglong2 n1 = __ldg((const ulonglong2*)(wn + 4));
        const float* ap = (k < KA ? baseA : baseB) + k * SS;
        ulonglong2 aA = *(const ulonglong2*)(ap);        // batches b0..b0+3
        ulonglong2 aB = *(const ulonglong2*)(ap + 4);    // batches b0+4..b0+7
        fma2(acc[0][0], w0.x, aA.x); fma2(acc[0][1], w0.x, aA.y);
        fma2(acc[0][2], w0.x, aB.x); fma2(acc[0][3], w0.x, aB.y);
        fma2(acc[1][0], w0.y, aA.x); fma2(acc[1][1], w0.y, aA.y);
        fma2(acc[1][2], w0.y, aB.x); fma2(acc[1][3], w0.y, aB.y);
        fma2(acc[2][0], w1.x, aA.x); fma2(acc[2][1], w1.x, aA.y);
        fma2(acc[2][2], w1.x, aB.x); fma2(acc[2][3], w1.x, aB.y);
        fma2(acc[3][0], w1.y, aA.x); fma2(acc[3][1], w1.y, aA.y);
        fma2(acc[3][2], w1.y, aB.x); fma2(acc[3][3], w1.y, aB.y);
        w0 = n0; w1 = n1;
    }

    // epilogue: gates -> c update -> s
    float4 cv0 = *(const float4*)(shC + u * SS + b0);
    float4 cv1 = *(const float4*)(shC + u * SS + b0 + 4);
    float cb[8] = {cv0.x, cv0.y, cv0.z, cv0.w, cv1.x, cv1.y, cv1.z, cv1.w};
    float sb[8];
#pragma unroll
    for (int p = 0; p < 4; ++p) {
        float gi0, gi1, gf0, gf1, gg0, gg1, go0, go1;
        unpk(acc[0][p], gi0, gi1);
        unpk(acc[1][p], gf0, gf1);
        unpk(acc[2][p], gg0, gg1);
        unpk(acc[3][p], go0, go1);
        float cn0 = fsig(gf0) * cb[2 * p]     + fsig(gi0) * ftanh(gg0);
        float cn1 = fsig(gf1) * cb[2 * p + 1] + fsig(gi1) * ftanh(gg1);
        cb[2 * p]     = cn0;
        cb[2 * p + 1] = cn1;
        sb[2 * p]     = fsig(go0) * ftanh(cn0);
        sb[2 * p + 1] = fsig(go1) * ftanh(cn1);
    }
    *(float4*)(shC + u * SS + b0)       = make_float4(cb[0], cb[1], cb[2], cb[3]);
    *(float4*)(shC + u * SS + b0 + 4)   = make_float4(cb[4], cb[5], cb[6], cb[7]);
    *(float4*)(shOut + u * SS + b0)     = make_float4(sb[0], sb[1], sb[2], sb[3]);
    *(float4*)(shOut + u * SS + b0 + 4) = make_float4(sb[4], sb[5], sb[6], sb[7]);
}

// hp[64,32] = s[64,128] @ WhrT[128,32] with dup'd weights WTd[k][64].
// 256 active threads: colgroup cg = tid&7 (cols 4cg..4cg+3),
// batch pair p = tid>>3 (batches 2p, 2p+1).
__device__ __forceinline__ void proj_gemm(
    const float* __restrict__ WTd, const float* shS, float* shHdst,
    float* outp, int tid)
{
    if (tid >= 256) return;
    const int cg = tid & 7;
    const int p  = tid >> 3;
    ull acc[4] = {0ull, 0ull, 0ull, 0ull};
    const float* Wu = WTd + 8 * cg;
#pragma unroll 4
    for (int k = 0; k < 128; ++k) {
        ulonglong2 wA = __ldg((const ulonglong2*)(Wu + k * 64));
        ulonglong2 wB = __ldg((const ulonglong2*)(Wu + k * 64 + 4));
        ull a = *(const ull*)(shS + k * SS + 2 * p);
        fma2(acc[0], wA.x, a);
        fma2(acc[1], wA.y, a);
        fma2(acc[2], wB.x, a);
        fma2(acc[3], wB.y, a);
    }
    float lo[4], hi[4];
#pragma unroll
    for (int j = 0; j < 4; ++j) {
        unpk(acc[j], lo[j], hi[j]);
        shHdst[(4 * cg + j) * SS + 2 * p]     = lo[j];
        shHdst[(4 * cg + j) * SS + 2 * p + 1] = hi[j];
    }
    if (outp) {
        *(float4*)(outp + (size_t)(2 * p) * 512 + 4 * cg) =
            make_float4(lo[0], lo[1], lo[2], lo[3]);
        *(float4*)(outp + (size_t)(2 * p + 1) * 512 + 4 * cg) =
            make_float4(hi[0], hi[1], hi[2], hi[3]);
    }
}

// v[8,64] = h_new[64,128] @ WpT[128,8] + bp, dup'd WpTd[k][16].
// 64 active threads: cg = tid&1 (cols 4cg..), pair p = tid>>1.
__device__ __forceinline__ void wp_gemm(
    const float* shS, float* shV, int tid)
{
    if (tid >= 64) return;
    const int cg = tid & 1;
    const int p  = tid >> 1;
    ulonglong2 bA = *(const ulonglong2*)(g_bpd + 8 * cg);
    ulonglong2 bB = *(const ulonglong2*)(g_bpd + 8 * cg + 4);
    ull acc[4] = {bA.x, bA.y, bB.x, bB.y};
    const float* Wu = g_WpT + 8 * cg;
#pragma unroll 4
    for (int k = 0; k < 128; ++k) {
        ulonglong2 wA = __ldg((const ulonglong2*)(Wu + k * 16));
        ulonglong2 wB = __ldg((const ulonglong2*)(Wu + k * 16 + 4));
        ull a = *(const ull*)(shS + k * SS + 2 * p);
        fma2(acc[0], wA.x, a);
        fma2(acc[1], wA.y, a);
        fma2(acc[2], wB.x, a);
        fma2(acc[3], wB.y, a);
    }
#pragma unroll
    for (int j = 0; j < 4; ++j) {
        float lo, hi;
        unpk(acc[j], lo, hi);
        shV[(4 * cg + j) * SS + 2 * p]     = lo;
        shV[(4 * cg + j) * SS + 2 * p + 1] = hi;
    }
}

// quantum measurement physics for one batch element b (0..63)
__device__ __forceinline__ void physics(const float* shV, const float* shRHO,
                                        float* shX, int b)
{
    float Mr[2][2][2], Mi[2][2][2];
#pragma unroll
    for (int q = 0; q < 2; ++q) {
        float ar = shV[(q * 4 + 0) * SS + b];
        float ai = shV[(q * 4 + 1) * SS + b];
        float br = shV[(q * 4 + 2) * SS + b];
        float bi = shV[(q * 4 + 3) * SS + b];
        float n00 = ar * ar + ai * ai;
        float n11 = br * br + bi * bi;
        float inv = 1.0f / (n00 + n11);
        float pr = (ar * br + ai * bi) * inv;
        float pi = (ai * br - ar * bi) * inv;
        Mr[q][0][0] = n00 * inv; Mi[q][0][0] = 0.f;
        Mr[q][0][1] = pr;        Mi[q][0][1] = pi;
        Mr[q][1][0] = pr;        Mi[q][1][0] = -pi;
        Mr[q][1][1] = n11 * inv; Mi[q][1][1] = 0.f;
    }
    const float* rp = shRHO + b * 33;
    float m = 0.f;
#pragma unroll
    for (int a = 0; a < 2; ++a)
#pragma unroll
        for (int c = 0; c < 2; ++c)
#pragma unroll
            for (int b2 = 0; b2 < 2; ++b2)
#pragma unroll
                for (int d = 0; d < 2; ++d) {
                    float tr_ = Mr[0][a][c] * Mr[1][b2][d] - Mi[0][a][c] * Mi[1][b2][d];
                    float ti_ = Mr[0][a][c] * Mi[1][b2][d] + Mi[0][a][c] * Mr[1][b2][d];
                    int row = c * 2 + d, col = a * 2 + b2;
                    float rr = rp[row * 4 + col];
                    float ri = rp[16 + row * 4 + col];
                    m += tr_ * rr - ti_ * ri;
                }
    shX[0 * SS + b] = m;
#pragma unroll
    for (int q = 0; q < 2; ++q)
#pragma unroll
        for (int i = 0; i < 2; ++i)
#pragma unroll
            for (int j = 0; j < 2; ++j) {
                int base = 1 + 8 * q + 4 * i + 2 * j;
                shX[base * SS + b]       = Mr[q][i][j];
                shX[(base + 1) * SS + b] = Mi[q][i][j];
            }
}

__global__ void __launch_bounds__(NTH, 1) fused_kernel(
    const float* __restrict__ meas, const float* __restrict__ basis_r,
    const float* __restrict__ basis_i, const float* __restrict__ rho,
    const float* __restrict__ h0in, const float* __restrict__ c0in,
    float* __restrict__ out)
{
    extern __shared__ float sm[];
    float* shX   = sm + OFF_X;
    float* shCC  = sm + OFF_CC;
    float* shH0  = sm + OFF_H0;
    float* shC0  = sm + OFF_C0;
    float* shH1  = sm + OFF_H1;
    float* shC1  = sm + OFF_C1;
    float* shRHO = sm + OFF_RHO;
    float* shV   = sm + OFF_V;

    const int tid = threadIdx.x;
    const int b0g = blockIdx.x * BT;

    // ---- init loads ----
    for (int i = tid; i < BT; i += NTH)
        shX[0 * SS + i] = meas[b0g + i];
    for (int i = tid; i < BT * 8; i += NTH) {
        int b = i >> 3, e = i & 7;
        shX[(1 + 2 * e) * SS + b] = basis_r[(size_t)(b0g + b) * 8 + e];
        shX[(2 + 2 * e) * SS + b] = basis_i[(size_t)(b0g + b) * 8 + e];
    }
    for (int i = tid; i < BT * 32; i += NTH) {
        int b = i >> 5, e = i & 31;
        shRHO[b * 33 + e] = rho[(size_t)(b0g + b) * 32 + e];
    }
    for (int i = tid; i < BT * 128; i += NTH) {
        int b = i >> 7, u = i & 127;
        sm[OFF_HCA + u * SS + b] = h0in[(size_t)(b0g + b) * 128 + u];
        shCC[u * SS + b]         = c0in[(size_t)(b0g + b) * 128 + u];
    }
    // zero H0, C0, H1, C1 (320 contiguous rows)
    for (int i = tid; i < 320 * SS; i += NTH)
        sm[OFF_H0 + i] = 0.f;
    __syncthreads();

    const int u  = tid & 127;
    const int b0 = (tid >> 7) * 8;

    float* hcur = sm + OFF_HCA;   // cell h state (valid)
    float* hnxt = sm + OFF_HCB;   // scratch: s staging + next cell h

    for (int t = 0; t < 16; ++t) {
        // LSTM0: reads X,H0,C0; writes s->hnxt, C0
        lstm_step<17, 32>(g_W0, g_b0, shX, shH0, shC0, hnxt, u, b0);
        __syncthreads();
        proj_gemm(g_Whr0T, hnxt, shH0, nullptr, tid);
        __syncthreads();
        // LSTM1: reads H0,H1,C1; writes s->hnxt, C1
        lstm_step<32, 32>(g_W1, g_b1, shH0, shH1, shC1, hnxt, u, b0);
        __syncthreads();
        proj_gemm(g_Whr1T, hnxt, shH1,
                  out + (size_t)b0g * 512 + (size_t)t * 32, tid);
        __syncthreads();

        if (t < 15) {
            // cell: reads X, hcur, CC; writes h_new->hnxt, CC
            lstm_step<17, 128>(g_Wc, g_bc, shX, hcur, shCC, hnxt, u, b0);
            __syncthreads();
            wp_gemm(hnxt, shV, tid);     // v = h_new @ WpT + bp
            __syncthreads();
            if (tid < BT) physics(shV, shRHO, shX, tid);
            __syncthreads();
            float* tmp = hcur; hcur = hnxt; hnxt = tmp;
        }
    }
}

extern "C" void kernel_launch(void* const* d_in, const int* in_sizes, int n_in,
                              void* d_out, int out_size)
{
    const float* meas   = (const float*)d_in[0];
    const float* br     = (const float*)d_in[1];
    const float* bi     = (const float*)d_in[2];
    const float* rho    = (const float*)d_in[3];
    const float* h0     = (const float*)d_in[4];
    const float* c0     = (const float*)d_in[5];
    const float* Wihc   = (const float*)d_in[6];
    const float* Whhc   = (const float*)d_in[7];
    const float* bihc   = (const float*)d_in[8];
    const float* bhhc   = (const float*)d_in[9];
    const float* Wp     = (const float*)d_in[10];
    const float* bp     = (const float*)d_in[11];
    const float* Wih0   = (const float*)d_in[12];
    const float* Whh0   = (const float*)d_in[13];
    const float* bih0   = (const float*)d_in[14];
    const float* bhh0   = (const float*)d_in[15];
    const float* Whr0   = (const float*)d_in[16];
    const float* Wih1   = (const float*)d_in[17];
    const float* Whh1   = (const float*)d_in[18];
    const float* bih1   = (const float*)d_in[19];
    const float* bhh1   = (const float*)d_in[20];
    const float* Whr1   = (const float*)d_in[21];

    int B = in_sizes[0];
    int nblocks = B / BT;

    cudaFuncSetAttribute(fused_kernel,
                         cudaFuncAttributeMaxDynamicSharedMemorySize,
                         SMEM_BYTES);

    prep_kernel<<<256, 256>>>(Wihc, Whhc, bihc, bhhc, Wp, bp,
                              Wih0, Whh0, bih0, bhh0, Whr0,
                              Wih1, Whh1, bih1, bhh1, Whr1);

    fused_kernel<<<nblocks, NTH, SMEM_BYTES>>>(
        meas, br, bi, rho, h0, c0, (float*)d_out);
}

// round 6
// speedup vs baseline: 1.2889x; 1.2889x over previous
#include <cuda_runtime.h>

// ---------------------------------------------------------------------------
// Fused LSTMMeasurementPredictor — round 6
//   B=131072, H=128, NQ=2, P=32, D_IN=17, T=16
// 512 threads / 32-batch tile. FFMA2 gate-pair accumulators:
//   - weights COMPACT in global (1 LDG.128 = gates i,f,g,o of one unit,
//     reused by all batch groups through L1)
//   - activations DUPLICATED in smem: row k holds (a_b, a_b) pairs, so
//     LDS.128 yields ready FFMA2 broadcast operands. ZERO movs in inner loop.
// ---------------------------------------------------------------------------

#define NTH 512
#define BT  32
#define SSD 68   // stride (floats) of duplicated act rows  (64 data + pad)
#define SSN 36   // stride (floats) of non-dup c rows        (32 data + pad)

constexpr int OFF_X   = 0;                    // 17  dup rows : x
constexpr int OFF_HCA = OFF_X   + 17  * SSD;  // 128 dup rows : cell h (ping)
constexpr int OFF_HCB = OFF_HCA + 128 * SSD;  // 128 dup rows : cell h (pong)/s
constexpr int OFF_H0  = OFF_HCB + 128 * SSD;  // 32  dup rows : lstm0 proj h
constexpr int OFF_H1  = OFF_H0  + 32  * SSD;  // 32  dup rows : lstm1 proj h
constexpr int OFF_CC  = OFF_H1  + 32  * SSD;  // 128 rows : cell c
constexpr int OFF_C0  = OFF_CC  + 128 * SSN;  // 128 rows : lstm0 c
constexpr int OFF_C1  = OFF_C0  + 128 * SSN;  // 128 rows : lstm1 c
constexpr int OFF_RHO = OFF_C1  + 128 * SSN;  // 32*33    : rho
constexpr int OFF_V   = OFF_RHO + 32 * 33;    // 8 dup rows : projector v
constexpr int SMEM_FLOATS = OFF_V + 8 * SSD;
constexpr int SMEM_BYTES  = SMEM_FLOATS * 4;  // ~150 KB

// compact packed weights: W[k][512], column jp = u*4 + gate (i,f,g,o).
// +1024 floats pad so distance-2 prefetch can overshoot by 2 rows.
__device__ __align__(16) float g_Wc[145 * 512 + 1024];
__device__ __align__(16) float g_bc[512];
__device__ __align__(16) float g_W0[49 * 512 + 1024];
__device__ __align__(16) float g_b0[512];
__device__ __align__(16) float g_W1[64 * 512 + 1024];
__device__ __align__(16) float g_b1[512];
__device__ __align__(16) float g_Whr0T[128 * 32];   // [k][n] compact
__device__ __align__(16) float g_Whr1T[128 * 32];
__device__ __align__(16) float g_WpT[128 * 8];      // [k][n] compact

__global__ void prep_kernel(
    const float* __restrict__ Wihc, const float* __restrict__ Whhc,
    const float* __restrict__ bihc, const float* __restrict__ bhhc,
    const float* __restrict__ Wp,
    const float* __restrict__ Wih0, const float* __restrict__ Whh0,
    const float* __restrict__ bih0, const float* __restrict__ bhh0,
    const float* __restrict__ Whr0,
    const float* __restrict__ Wih1, const float* __restrict__ Whh1,
    const float* __restrict__ bih1, const float* __restrict__ bhh1,
    const float* __restrict__ Whr1)
{
    int i0 = blockIdx.x * blockDim.x + threadIdx.x;
    int stride = gridDim.x * blockDim.x;

    for (int i = i0; i < 145 * 512; i += stride) {
        int k = i >> 9, jp = i & 511;
        int u = jp >> 2, g = jp & 3, j = g * 128 + u;
        g_Wc[i] = (k < 17) ? Wihc[j * 17 + k] : Whhc[j * 128 + (k - 17)];
    }
    for (int i = i0; i < 49 * 512; i += stride) {
        int k = i >> 9, jp = i & 511;
        int u = jp >> 2, g = jp & 3, j = g * 128 + u;
        g_W0[i] = (k < 17) ? Wih0[j * 17 + k] : Whh0[j * 32 + (k - 17)];
    }
    for (int i = i0; i < 64 * 512; i += stride) {
        int k = i >> 9, jp = i & 511;
        int u = jp >> 2, g = jp & 3, j = g * 128 + u;
        g_W1[i] = (k < 32) ? Wih1[j * 32 + k] : Whh1[j * 32 + (k - 32)];
    }
    for (int i = i0; i < 1024; i += stride) {
        g_Wc[145 * 512 + i] = 0.f;
        g_W0[49 * 512 + i] = 0.f;
        g_W1[64 * 512 + i] = 0.f;
    }
    for (int i = i0; i < 512; i += stride) {
        int u = i >> 2, g = i & 3, j = g * 128 + u;
        g_bc[i] = bihc[j] + bhhc[j];
        g_b0[i] = bih0[j] + bhh0[j];
        g_b1[i] = bih1[j] + bhh1[j];
    }
    for (int i = i0; i < 128 * 32; i += stride) {
        int k = i >> 5, n = i & 31;
        g_Whr0T[i] = Whr0[n * 128 + k];
        g_Whr1T[i] = Whr1[n * 128 + k];
    }
    for (int i = i0; i < 128 * 8; i += stride) {
        int k = i >> 3, n = i & 7;
        g_WpT[i] = Wp[n * 128 + k];
    }
}

// ---------------------------------------------------------------------------
typedef unsigned long long ull;

__device__ __forceinline__ void fma2(ull& acc, ull a, ull b) {
    asm("fma.rn.f32x2 %0, %1, %2, %0;" : "+l"(acc) : "l"(a), "l"(b));
}
__device__ __forceinline__ void unpk(ull v, float& lo, float& hi) {
    asm("mov.b64 {%0, %1}, %2;" : "=f"(lo), "=f"(hi) : "l"(v));
}

__device__ __forceinline__ float fsig(float x) {
    return __fdividef(1.0f, 1.0f + __expf(-x));
}
__device__ __forceinline__ float ftanh(float x) {
    return __fdividef(2.0f, 1.0f + __expf(-2.0f * x)) - 1.0f;
}

// LSTM step: G[32,512] = [A(KA); B(KB)] @ W + bias, then gate update.
// Thread: unit u = tid&127 (gate cols 4u..4u+3), batches b0=(tid>>7)*8..+7.
// Weight LDG.128 -> ulonglong2 lanes (w_i,w_f),(w_g,w_o) : direct FFMA2 ops.
// Act rows duplicated: LDS.128 -> (a_b,a_b),(a_{b+1},a_{b+1}).
// acc[0][p] = (g_i, g_f), acc[1][p] = (g_g, g_o) for batch b0+p.
// NO internal barrier: {shC, shOut} elementwise-owned by this thread.
template <int KA, int KB>
__device__ __forceinline__ void lstm_step(
    const float* __restrict__ W, const float* __restrict__ bias,
    const float* shA, const float* shB, float* shC, float* shOut,
    int u, int b0)
{
    constexpr int K = KA + KB;
    ull acc[2][8];
    {
        ulonglong2 bs = *(const ulonglong2*)(bias + 4 * u);  // (bi,bf),(bg,bo)
#pragma unroll
        for (int p = 0; p < 8; ++p) { acc[0][p] = bs.x; acc[1][p] = bs.y; }
    }
    const float* Wu    = W + 4 * u;
    const float* baseA = shA + 2 * b0;
    const float* baseB = shB + 2 * b0 - KA * SSD;

    ulonglong2 w0 = __ldg((const ulonglong2*)(Wu));
    ulonglong2 w1 = __ldg((const ulonglong2*)(Wu + 512));
#pragma unroll 4
    for (int k = 0; k < K; ++k) {
        ulonglong2 wn = __ldg((const ulonglong2*)(Wu + (k + 2) * 512)); // pad-safe
        const float* ap = (k < KA ? baseA : baseB) + k * SSD;
#pragma unroll
        for (int j = 0; j < 4; ++j) {
            ulonglong2 a = *(const ulonglong2*)(ap + 4 * j);  // 2 dup'd batches
            fma2(acc[0][2 * j],     w0.x, a.x);
            fma2(acc[0][2 * j + 1], w0.x, a.y);
            fma2(acc[1][2 * j],     w0.y, a.x);
            fma2(acc[1][2 * j + 1], w0.y, a.y);
        }
        w0 = w1; w1 = wn;
    }

    // epilogue: gates -> c update -> s (dup'd write)
    const float* cpr = shC + u * SSN + b0;
    float4 cv0 = *(const float4*)(cpr);
    float4 cv1 = *(const float4*)(cpr + 4);
    float cb[8] = {cv0.x, cv0.y, cv0.z, cv0.w, cv1.x, cv1.y, cv1.z, cv1.w};
    float sb[8];
#pragma unroll
    for (int p = 0; p < 8; ++p) {
        float gi, gf, gg, go;
        unpk(acc[0][p], gi, gf);
        unpk(acc[1][p], gg, go);
        float cn = fsig(gf) * cb[p] + fsig(gi) * ftanh(gg);
        cb[p] = cn;
        sb[p] = fsig(go) * ftanh(cn);
    }
    float* cpw = shC + u * SSN + b0;
    *(float4*)(cpw)     = make_float4(cb[0], cb[1], cb[2], cb[3]);
    *(float4*)(cpw + 4) = make_float4(cb[4], cb[5], cb[6], cb[7]);
    float* op = shOut + u * SSD + 2 * b0;
#pragma unroll
    for (int j = 0; j < 4; ++j)
        *(float4*)(op + 4 * j) =
            make_float4(sb[2 * j], sb[2 * j], sb[2 * j + 1], sb[2 * j + 1]);
}

// hp[32,32] = s[32,128] @ WhrT[128,32]. 256 active threads:
// cg = tid&7 -> cols 4cg..4cg+3, b = tid>>3 (one batch).
__device__ __forceinline__ void proj_gemm(
    const float* __restrict__ WT, const float* shS, float* shHdst,
    float* outp, int tid)
{
    if (tid >= 256) return;
    const int cg = tid & 7;
    const int b  = tid >> 3;
    ull acc0 = 0ull, acc1 = 0ull;
    const float* Wu = WT + 4 * cg;
#pragma unroll 4
    for (int k = 0; k < 128; ++k) {
        ulonglong2 w = __ldg((const ulonglong2*)(Wu + k * 32));
        ull a = *(const ull*)(shS + k * SSD + 2 * b);   // (a_b, a_b)
        fma2(acc0, w.x, a);
        fma2(acc1, w.y, a);
    }
    float v0, v1, v2, v3;
    unpk(acc0, v0, v1);
    unpk(acc1, v2, v3);
    float* hp = shHdst + (4 * cg) * SSD + 2 * b;
    *(float2*)(hp)           = make_float2(v0, v0);
    *(float2*)(hp + SSD)     = make_float2(v1, v1);
    *(float2*)(hp + 2 * SSD) = make_float2(v2, v2);
    *(float2*)(hp + 3 * SSD) = make_float2(v3, v3);
    if (outp)
        *(float4*)(outp + (size_t)b * 512 + 4 * cg) = make_float4(v0, v1, v2, v3);
}

// v[8,32] = h_new[32,128] @ WpT[128,8] + bp. 128 active threads:
// cp = tid&3 -> cols 2cp,2cp+1 ; b = tid>>2.
__device__ __forceinline__ void wp_gemm(
    const float* __restrict__ bp, const float* shS, float* shV, int tid)
{
    if (tid >= 128) return;
    const int cp = tid & 3;
    const int b  = tid >> 2;
    ull acc = __ldg((const ull*)(bp + 2 * cp));
    const float* Wu = g_WpT + 2 * cp;
#pragma unroll 4
    for (int k = 0; k < 128; ++k) {
        ull w = __ldg((const ull*)(Wu + k * 8));
        ull a = *(const ull*)(shS + k * SSD + 2 * b);
        fma2(acc, w, a);
    }
    float v0, v1;
    unpk(acc, v0, v1);
    float* vp = shV + (2 * cp) * SSD + 2 * b;
    *(float2*)(vp)       = make_float2(v0, v0);
    *(float2*)(vp + SSD) = make_float2(v1, v1);
}

// quantum measurement physics for one batch element b (0..31); dup'd X write
__device__ __forceinline__ void physics(const float* shV, const float* shRHO,
                                        float* shX, int b)
{
    float Mr[2][2][2], Mi[2][2][2];
#pragma unroll
    for (int q = 0; q < 2; ++q) {
        float ar = shV[(q * 4 + 0) * SSD + 2 * b];
        float ai = shV[(q * 4 + 1) * SSD + 2 * b];
        float br = shV[(q * 4 + 2) * SSD + 2 * b];
        float bi = shV[(q * 4 + 3) * SSD + 2 * b];
        float n00 = ar * ar + ai * ai;
        float n11 = br * br + bi * bi;
        float inv = 1.0f / (n00 + n11);
        float pr = (ar * br + ai * bi) * inv;
        float pi = (ai * br - ar * bi) * inv;
        Mr[q][0][0] = n00 * inv; Mi[q][0][0] = 0.f;
        Mr[q][0][1] = pr;        Mi[q][0][1] = pi;
        Mr[q][1][0] = pr;        Mi[q][1][0] = -pi;
        Mr[q][1][1] = n11 * inv; Mi[q][1][1] = 0.f;
    }
    const float* rp = shRHO + b * 33;
    float m = 0.f;
#pragma unroll
    for (int a = 0; a < 2; ++a)
#pragma unroll
        for (int c = 0; c < 2; ++c)
#pragma unroll
            for (int b2 = 0; b2 < 2; ++b2)
#pragma unroll
                for (int d = 0; d < 2; ++d) {
                    float tr_ = Mr[0][a][c] * Mr[1][b2][d] - Mi[0][a][c] * Mi[1][b2][d];
                    float ti_ = Mr[0][a][c] * Mi[1][b2][d] + Mi[0][a][c] * Mr[1][b2][d];
                    int row = c * 2 + d, col = a * 2 + b2;
                    float rr = rp[row * 4 + col];
                    float ri = rp[16 + row * 4 + col];
                    m += tr_ * rr - ti_ * ri;
                }
    shX[2 * b] = m; shX[2 * b + 1] = m;
#pragma unroll
    for (int q = 0; q < 2; ++q)
#pragma unroll
        for (int i = 0; i < 2; ++i)
#pragma unroll
            for (int j = 0; j < 2; ++j) {
                int base = 1 + 8 * q + 4 * i + 2 * j;
                float* xr = shX + base * SSD + 2 * b;
                xr[0] = Mr[q][i][j]; xr[1] = Mr[q][i][j];
                xr[SSD] = Mi[q][i][j]; xr[SSD + 1] = Mi[q][i][j];
            }
}

__global__ void __launch_bounds__(NTH, 1) fused_kernel(
    const float* __restrict__ meas, const float* __restrict__ basis_r,
    const float* __restrict__ basis_i, const float* __restrict__ rho,
    const float* __restrict__ h0in, const float* __restrict__ c0in,
    const float* __restrict__ bp, float* __restrict__ out)
{
    extern __shared__ float sm[];
    float* shX   = sm + OFF_X;
    float* shH0  = sm + OFF_H0;
    float* shH1  = sm + OFF_H1;
    float* shCC  = sm + OFF_CC;
    float* shC0  = sm + OFF_C0;
    float* shC1  = sm + OFF_C1;
    float* shRHO = sm + OFF_RHO;
    float* shV   = sm + OFF_V;

    const int tid = threadIdx.x;
    const int b0g = blockIdx.x * BT;

    // ---- init loads (dup'd act rows) ----
    for (int i = tid; i < BT; i += NTH) {
        float m = meas[b0g + i];
        shX[2 * i] = m; shX[2 * i + 1] = m;
    }
    for (int i = tid; i < BT * 8; i += NTH) {
        int b = i >> 3, e = i & 7;
        float vr = basis_r[(size_t)(b0g + b) * 8 + e];
        float vi = basis_i[(size_t)(b0g + b) * 8 + e];
        float* xr = shX + (1 + 2 * e) * SSD + 2 * b;
        float* xi = shX + (2 + 2 * e) * SSD + 2 * b;
        xr[0] = vr; xr[1] = vr;
        xi[0] = vi; xi[1] = vi;
    }
    for (int i = tid; i < BT * 32; i += NTH) {
        int b = i >> 5, e = i & 31;
        shRHO[b * 33 + e] = rho[(size_t)(b0g + b) * 32 + e];
    }
    for (int i = tid; i < BT * 128; i += NTH) {
        int b = i >> 7, u = i & 127;
        float hv = h0in[(size_t)(b0g + b) * 128 + u];
        sm[OFF_HCA + u * SSD + 2 * b]     = hv;
        sm[OFF_HCA + u * SSD + 2 * b + 1] = hv;
        shCC[u * SSN + b] = c0in[(size_t)(b0g + b) * 128 + u];
    }
    // zero H0,H1 (dup, contiguous) and C0,C1 (contiguous)
    for (int i = tid; i < 64 * SSD; i += NTH) sm[OFF_H0 + i] = 0.f;
    for (int i = tid; i < 256 * SSN; i += NTH) sm[OFF_C0 + i] = 0.f;
    __syncthreads();

    const int u  = tid & 127;
    const int b0 = (tid >> 7) * 8;

    float* hcur = sm + OFF_HCA;
    float* hnxt = sm + OFF_HCB;

    for (int t = 0; t < 16; ++t) {
        // LSTM0: reads X,H0,C0; writes s->hnxt (dup), C0
        lstm_step<17, 32>(g_W0, g_b0, shX, shH0, shC0, hnxt, u, b0);
        __syncthreads();
        proj_gemm(g_Whr0T, hnxt, shH0, nullptr, tid);
        __syncthreads();
        // LSTM1: reads H0,H1,C1; writes s->hnxt, C1
        lstm_step<32, 32>(g_W1, g_b1, shH0, shH1, shC1, hnxt, u, b0);
        __syncthreads();
        proj_gemm(g_Whr1T, hnxt, shH1,
                  out + (size_t)b0g * 512 + (size_t)t * 32, tid);
        __syncthreads();

        if (t < 15) {
            // cell: reads X, hcur, CC; writes h_new->hnxt (dup), CC
            lstm_step<17, 128>(g_Wc, g_bc, shX, hcur, shCC, hnxt, u, b0);
            __syncthreads();
            wp_gemm(bp, hnxt, shV, tid);     // v = h_new @ WpT + bp
            __syncthreads();
            if (tid < BT) physics(shV, shRHO, shX, tid);
            __syncthreads();
            float* tmp = hcur; hcur = hnxt; hnxt = tmp;
        }
    }
}

extern "C" void kernel_launch(void* const* d_in, const int* in_sizes, int n_in,
                              void* d_out, int out_size)
{
    const float* meas   = (const float*)d_in[0];
    const float* br     = (const float*)d_in[1];
    const float* bi     = (const float*)d_in[2];
    const float* rho    = (const float*)d_in[3];
    const float* h0     = (const float*)d_in[4];
    const float* c0     = (const float*)d_in[5];
    const float* Wihc   = (const float*)d_in[6];
    const float* Whhc   = (const float*)d_in[7];
    const float* bihc   = (const float*)d_in[8];
    const float* bhhc   = (const float*)d_in[9];
    const float* Wp     = (const float*)d_in[10];
    const float* bp     = (const float*)d_in[11];
    const float* Wih0   = (const float*)d_in[12];
    const float* Whh0   = (const float*)d_in[13];
    const float* bih0   = (const float*)d_in[14];
    const float* bhh0   = (const float*)d_in[15];
    const float* Whr0   = (const float*)d_in[16];
    const float* Wih1   = (const float*)d_in[17];
    const float* Whh1   = (const float*)d_in[18];
    const float* bih1   = (const float*)d_in[19];
    const float* bhh1   = (const float*)d_in[20];
    const float* Whr1   = (const float*)d_in[21];

    int B = in_sizes[0];
    int nblocks = B / BT;

    cudaFuncSetAttribute(fused_kernel,
                         cudaFuncAttributeMaxDynamicSharedMemorySize,
                         SMEM_BYTES);

    prep_kernel<<<128, 256>>>(Wihc, Whhc, bihc, bhhc, Wp,
                              Wih0, Whh0, bih0, bhh0, Whr0,
                              Wih1, Whh1, bih1, bhh1, Whr1);

    fused_kernel<<<nblocks, NTH, SMEM_BYTES>>>(
        meas, br, bi, rho, h0, c0, bp, (float*)d_out);
}

// round 7
// speedup vs baseline: 1.6852x; 1.3075x over previous
#include <cuda_runtime.h>

// ---------------------------------------------------------------------------
// Fused LSTMMeasurementPredictor — round 7
//   B=131072, H=128, NQ=2, P=32, D_IN=17, T=16
// 1024 threads / 64-batch tile (occ 50%). R4's proven operand economy:
// compact weights (1 LDG.128 = 4 gate cols, L1-reused by all 32 warps),
// plain smem acts, FFMA2 batch-pair accumulators. Per-thread tile halved to
// 1 unit x 8 batches so acc = 32 regs fits the 64-reg budget at 1024 thr.
// ---------------------------------------------------------------------------

#define NTH 1024
#define BT  64
#define SS  68   // padded row stride (floats) for [K][64] smem buffers

constexpr int OFF_X   = 0;                   // 17  rows : x
constexpr int OFF_HCA = OFF_X   + 17  * SS;  // 128 rows : cell h (ping)
constexpr int OFF_HCB = OFF_HCA + 128 * SS;  // 128 rows : cell h (pong) / s staging
constexpr int OFF_CC  = OFF_HCB + 128 * SS;  // 128 rows : cell c
constexpr int OFF_H0  = OFF_CC  + 128 * SS;  // 32  rows : lstm0 proj h
constexpr int OFF_C0  = OFF_H0  + 32  * SS;  // 128 rows : lstm0 c
constexpr int OFF_H1  = OFF_C0  + 128 * SS;  // 32  rows : lstm1 proj h
constexpr int OFF_C1  = OFF_H1  + 32  * SS;  // 128 rows : lstm1 c
constexpr int OFF_RHO = OFF_C1  + 128 * SS;  // 64*33    : rho
constexpr int OFF_V   = OFF_RHO + 64 * 33;   // 8 rows   : projector v
constexpr int SMEM_FLOATS = OFF_V + 8 * SS;
constexpr int SMEM_BYTES  = SMEM_FLOATS * 4; // ~202 KB

// compact packed weights: W[k][512], column jp = u*4 + gate (i,f,g,o).
// +1024 floats pad so the distance-2 prefetch can overshoot by 2 rows.
__device__ __align__(16) float g_Wc[145 * 512 + 1024];
__device__ __align__(16) float g_bc[512];
__device__ __align__(16) float g_W0[49 * 512 + 1024];
__device__ __align__(16) float g_b0[512];
__device__ __align__(16) float g_W1[64 * 512 + 1024];
__device__ __align__(16) float g_b1[512];
__device__ __align__(16) float g_Whr0T[128 * 32];   // [k][n] compact
__device__ __align__(16) float g_Whr1T[128 * 32];
__device__ __align__(16) float g_WpT[128 * 8];      // [k][n] compact

__global__ void prep_kernel(
    const float* __restrict__ Wihc, const float* __restrict__ Whhc,
    const float* __restrict__ bihc, const float* __restrict__ bhhc,
    const float* __restrict__ Wp,
    const float* __restrict__ Wih0, const float* __restrict__ Whh0,
    const float* __restrict__ bih0, const float* __restrict__ bhh0,
    const float* __restrict__ Whr0,
    const float* __restrict__ Wih1, const float* __restrict__ Whh1,
    const float* __restrict__ bih1, const float* __restrict__ bhh1,
    const float* __restrict__ Whr1)
{
    int i0 = blockIdx.x * blockDim.x + threadIdx.x;
    int stride = gridDim.x * blockDim.x;

    for (int i = i0; i < 145 * 512; i += stride) {
        int k = i >> 9, jp = i & 511;
        int u = jp >> 2, g = jp & 3, j = g * 128 + u;
        g_Wc[i] = (k < 17) ? Wihc[j * 17 + k] : Whhc[j * 128 + (k - 17)];
    }
    for (int i = i0; i < 49 * 512; i += stride) {
        int k = i >> 9, jp = i & 511;
        int u = jp >> 2, g = jp & 3, j = g * 128 + u;
        g_W0[i] = (k < 17) ? Wih0[j * 17 + k] : Whh0[j * 32 + (k - 17)];
    }
    for (int i = i0; i < 64 * 512; i += stride) {
        int k = i >> 9, jp = i & 511;
        int u = jp >> 2, g = jp & 3, j = g * 128 + u;
        g_W1[i] = (k < 32) ? Wih1[j * 32 + k] : Whh1[j * 32 + (k - 32)];
    }
    for (int i = i0; i < 1024; i += stride) {
        g_Wc[145 * 512 + i] = 0.f;
        g_W0[49 * 512 + i] = 0.f;
        g_W1[64 * 512 + i] = 0.f;
    }
    for (int i = i0; i < 512; i += stride) {
        int u = i >> 2, g = i & 3, j = g * 128 + u;
        g_bc[i] = bihc[j] + bhhc[j];
        g_b0[i] = bih0[j] + bhh0[j];
        g_b1[i] = bih1[j] + bhh1[j];
    }
    for (int i = i0; i < 128 * 32; i += stride) {
        int k = i >> 5, n = i & 31;
        g_Whr0T[i] = Whr0[n * 128 + k];
        g_Whr1T[i] = Whr1[n * 128 + k];
    }
    for (int i = i0; i < 128 * 8; i += stride) {
        int k = i >> 3, n = i & 7;
        g_WpT[i] = Wp[n * 128 + k];
    }
}

// ---------------------------------------------------------------------------
typedef unsigned long long ull;

__device__ __forceinline__ void fma2(ull& acc, ull a, ull b) {
    asm("fma.rn.f32x2 %0, %1, %2, %0;" : "+l"(acc) : "l"(a), "l"(b));
}
__device__ __forceinline__ ull dup2(float x) {
    ull r;
    asm("mov.b64 %0, {%1, %1};" : "=l"(r) : "f"(x));
    return r;
}
__device__ __forceinline__ void unpk(ull v, float& lo, float& hi) {
    asm("mov.b64 {%0, %1}, %2;" : "=f"(lo), "=f"(hi) : "l"(v));
}

__device__ __forceinline__ float fsig(float x) {
    return __fdividef(1.0f, 1.0f + __expf(-x));
}
__device__ __forceinline__ float ftanh(float x) {
    return __fdividef(2.0f, 1.0f + __expf(-2.0f * x)) - 1.0f;
}

// LSTM step: G[64,512] = [A(KA); B(KB)] @ W + bias, then gate update.
// Thread: unit u = tid&127 (cols 4u..4u+3), batches b0=(tid>>7)*8 .. +7.
// acc[gate][pair], pair = batches (b0+2p, b0+2p+1)  -> 16 ull = 32 regs.
// Compact weights: 1 LDG.128 per k = all 4 gate cols of unit u; dup via MOV.
// NO internal barrier: {shC, shOut} elementwise-owned by this thread.
template <int KA, int KB>
__device__ __forceinline__ void lstm_step(
    const float* __restrict__ W, const float* __restrict__ bias,
    const float* shA, const float* shB, float* shC, float* shOut,
    int u, int b0)
{
    constexpr int K = KA + KB;
    ull acc[4][4];
    {
        float4 bs = *(const float4*)(bias + 4 * u);
        ull d0 = dup2(bs.x), d1 = dup2(bs.y), d2 = dup2(bs.z), d3 = dup2(bs.w);
#pragma unroll
        for (int p = 0; p < 4; ++p) {
            acc[0][p] = d0; acc[1][p] = d1; acc[2][p] = d2; acc[3][p] = d3;
        }
    }
    const float* Wu    = W + 4 * u;
    const float* baseA = shA + b0;
    const float* baseB = shB + b0 - KA * SS;   // so that base + k*SS is valid

    float4 w0 = __ldg((const float4*)(Wu));
    float4 w1 = __ldg((const float4*)(Wu + 512));
#pragma unroll 4
    for (int k = 0; k < K; ++k) {
        float4 wn = __ldg((const float4*)(Wu + (k + 2) * 512));   // pad-safe
        const float* ap = (k < KA ? baseA : baseB) + k * SS;
        ull wd0 = dup2(w0.x), wd1 = dup2(w0.y), wd2 = dup2(w0.z), wd3 = dup2(w0.w);
        ulonglong2 aA = *(const ulonglong2*)(ap);       // batches b0..b0+3
        ulonglong2 aB = *(const ulonglong2*)(ap + 4);   // batches b0+4..b0+7
        fma2(acc[0][0], wd0, aA.x); fma2(acc[0][1], wd0, aA.y);
        fma2(acc[0][2], wd0, aB.x); fma2(acc[0][3], wd0, aB.y);
        fma2(acc[1][0], wd1, aA.x); fma2(acc[1][1], wd1, aA.y);
        fma2(acc[1][2], wd1, aB.x); fma2(acc[1][3], wd1, aB.y);
        fma2(acc[2][0], wd2, aA.x); fma2(acc[2][1], wd2, aA.y);
        fma2(acc[2][2], wd2, aB.x); fma2(acc[2][3], wd2, aB.y);
        fma2(acc[3][0], wd3, aA.x); fma2(acc[3][1], wd3, aA.y);
        fma2(acc[3][2], wd3, aB.x); fma2(acc[3][3], wd3, aB.y);
        w0 = w1; w1 = wn;
    }

    // epilogue: gates -> c update -> s  (8 batches)
    float4 cv0 = *(const float4*)(shC + u * SS + b0);
    float4 cv1 = *(const float4*)(shC + u * SS + b0 + 4);
    float cb[8] = {cv0.x, cv0.y, cv0.z, cv0.w, cv1.x, cv1.y, cv1.z, cv1.w};
    float sb[8];
#pragma unroll
    for (int p = 0; p < 4; ++p) {
        float gi0, gi1, gf0, gf1, gg0, gg1, go0, go1;
        unpk(acc[0][p], gi0, gi1);
        unpk(acc[1][p], gf0, gf1);
        unpk(acc[2][p], gg0, gg1);
        unpk(acc[3][p], go0, go1);
        float cn0 = fsig(gf0) * cb[2 * p]     + fsig(gi0) * ftanh(gg0);
        float cn1 = fsig(gf1) * cb[2 * p + 1] + fsig(gi1) * ftanh(gg1);
        cb[2 * p]     = cn0;
        cb[2 * p + 1] = cn1;
        sb[2 * p]     = fsig(go0) * ftanh(cn0);
        sb[2 * p + 1] = fsig(go1) * ftanh(cn1);
    }
    *(float4*)(shC + u * SS + b0)       = make_float4(cb[0], cb[1], cb[2], cb[3]);
    *(float4*)(shC + u * SS + b0 + 4)   = make_float4(cb[4], cb[5], cb[6], cb[7]);
    *(float4*)(shOut + u * SS + b0)     = make_float4(sb[0], sb[1], sb[2], sb[3]);
    *(float4*)(shOut + u * SS + b0 + 4) = make_float4(sb[4], sb[5], sb[6], sb[7]);
}

// hp[64,32] = s[64,128] @ WhrT[128,32].  1024 threads:
// col pair c2 = tid&15 (cols 2c2, 2c2+1), batch b = tid>>4 (0..63).
// acc = (out_c0, out_c1) -> ull == float2, stored directly.
__device__ __forceinline__ void proj_gemm(
    const float* __restrict__ WT, const float* shS, float* shHdst,
    float* outp, int tid)
{
    const int c2 = tid & 15;
    const int b  = tid >> 4;
    ull acc = 0ull;
    const float* Wu = WT + 2 * c2;
#pragma unroll 8
    for (int k = 0; k < 128; ++k) {
        ull w = __ldg((const ull*)(Wu + k * 32));   // (w_c0, w_c1)
        ull a = dup2(shS[k * SS + b]);
        fma2(acc, w, a);
    }
    float v0, v1;
    unpk(acc, v0, v1);
    shHdst[(2 * c2) * SS + b]     = v0;
    shHdst[(2 * c2 + 1) * SS + b] = v1;
    if (outp) {
        *(ull*)(outp + (size_t)b * 512 + 2 * c2) = acc;   // (v0,v1) coalesced
    }
}

// quantum measurement physics for one batch element b (0..63)
__device__ __forceinline__ void physics(const float* shV, const float* shRHO,
                                        float* shX, int b)
{
    float Mr[2][2][2], Mi[2][2][2];
#pragma unroll
    for (int q = 0; q < 2; ++q) {
        float ar = shV[(q * 4 + 0) * SS + b];
        float ai = shV[(q * 4 + 1) * SS + b];
        float br = shV[(q * 4 + 2) * SS + b];
        float bi = shV[(q * 4 + 3) * SS + b];
        float n00 = ar * ar + ai * ai;
        float n11 = br * br + bi * bi;
        float inv = 1.0f / (n00 + n11);
        float pr = (ar * br + ai * bi) * inv;
        float pi = (ai * br - ar * bi) * inv;
        Mr[q][0][0] = n00 * inv; Mi[q][0][0] = 0.f;
        Mr[q][0][1] = pr;        Mi[q][0][1] = pi;
        Mr[q][1][0] = pr;        Mi[q][1][0] = -pi;
        Mr[q][1][1] = n11 * inv; Mi[q][1][1] = 0.f;
    }
    const float* rp = shRHO + b * 33;
    float m = 0.f;
#pragma unroll
    for (int a = 0; a < 2; ++a)
#pragma unroll
        for (int c = 0; c < 2; ++c)
#pragma unroll
            for (int b2 = 0; b2 < 2; ++b2)
#pragma unroll
                for (int d = 0; d < 2; ++d) {
                    float tr_ = Mr[0][a][c] * Mr[1][b2][d] - Mi[0][a][c] * Mi[1][b2][d];
                    float ti_ = Mr[0][a][c] * Mi[1][b2][d] + Mi[0][a][c] * Mr[1][b2][d];
                    int row = c * 2 + d, col = a * 2 + b2;
                    float rr = rp[row * 4 + col];
                    float ri = rp[16 + row * 4 + col];
                    m += tr_ * rr - ti_ * ri;
                }
    shX[0 * SS + b] = m;
#pragma unroll
    for (int q = 0; q < 2; ++q)
#pragma unroll
        for (int i = 0; i < 2; ++i)
#pragma unroll
            for (int j = 0; j < 2; ++j) {
                int base = 1 + 8 * q + 4 * i + 2 * j;
                shX[base * SS + b]       = Mr[q][i][j];
                shX[(base + 1) * SS + b] = Mi[q][i][j];
            }
}

__global__ void __launch_bounds__(NTH, 1) fused_kernel(
    const float* __restrict__ meas, const float* __restrict__ basis_r,
    const float* __restrict__ basis_i, const float* __restrict__ rho,
    const float* __restrict__ h0in, const float* __restrict__ c0in,
    const float* __restrict__ bp, float* __restrict__ out)
{
    extern __shared__ float sm[];
    float* shX   = sm + OFF_X;
    float* shCC  = sm + OFF_CC;
    float* shH0  = sm + OFF_H0;
    float* shC0  = sm + OFF_C0;
    float* shH1  = sm + OFF_H1;
    float* shC1  = sm + OFF_C1;
    float* shRHO = sm + OFF_RHO;
    float* shV   = sm + OFF_V;

    const int tid = threadIdx.x;
    const int b0g = blockIdx.x * BT;

    // ---- init loads ----
    for (int i = tid; i < BT; i += NTH)
        shX[0 * SS + i] = meas[b0g + i];
    for (int i = tid; i < BT * 8; i += NTH) {
        int b = i >> 3, e = i & 7;
        shX[(1 + 2 * e) * SS + b] = basis_r[(size_t)(b0g + b) * 8 + e];
        shX[(2 + 2 * e) * SS + b] = basis_i[(size_t)(b0g + b) * 8 + e];
    }
    for (int i = tid; i < BT * 32; i += NTH) {
        int b = i >> 5, e = i & 31;
        shRHO[b * 33 + e] = rho[(size_t)(b0g + b) * 32 + e];
    }
    for (int i = tid; i < BT * 128; i += NTH) {
        int b = i >> 7, u = i & 127;
        sm[OFF_HCA + u * SS + b] = h0in[(size_t)(b0g + b) * 128 + u];
        shCC[u * SS + b]         = c0in[(size_t)(b0g + b) * 128 + u];
    }
    // zero H0, C0, H1, C1 (320 contiguous rows)
    for (int i = tid; i < 320 * SS; i += NTH)
        sm[OFF_H0 + i] = 0.f;
    __syncthreads();

    const int u  = tid & 127;
    const int b0 = (tid >> 7) * 8;

    float* hcur = sm + OFF_HCA;   // cell h state (valid)
    float* hnxt = sm + OFF_HCB;   // scratch: s staging + next cell h

    for (int t = 0; t < 16; ++t) {
        // LSTM0: reads X,H0,C0; writes s->hnxt, C0
        lstm_step<17, 32>(g_W0, g_b0, shX, shH0, shC0, hnxt, u, b0);
        __syncthreads();
        proj_gemm(g_Whr0T, hnxt, shH0, nullptr, tid);
        __syncthreads();
        // LSTM1: reads H0,H1,C1; writes s->hnxt, C1
        lstm_step<32, 32>(g_W1, g_b1, shH0, shH1, shC1, hnxt, u, b0);
        __syncthreads();
        proj_gemm(g_Whr1T, hnxt, shH1,
                  out + (size_t)b0g * 512 + (size_t)t * 32, tid);
        __syncthreads();

        if (t < 15) {
            // cell: reads X, hcur, CC; writes h_new->hnxt, CC
            lstm_step<17, 128>(g_Wc, g_bc, shX, hcur, shCC, hnxt, u, b0);
            __syncthreads();
            // projector v[8,64] = h_new @ WpT + bp  (512 active threads)
            if (tid < 512) {
                int nn = tid >> 6, bb = tid & 63;
                float a = __ldg(&bp[nn]);
#pragma unroll 8
                for (int k = 0; k < 128; ++k)
                    a += hnxt[k * SS + bb] * __ldg(&g_WpT[k * 8 + nn]);
                shV[nn * SS + bb] = a;
            }
            __syncthreads();
            if (tid < BT) physics(shV, shRHO, shX, tid);
            __syncthreads();
            float* tmp = hcur; hcur = hnxt; hnxt = tmp;
        }
    }
}

extern "C" void kernel_launch(void* const* d_in, const int* in_sizes, int n_in,
                              void* d_out, int out_size)
{
    const float* meas   = (const float*)d_in[0];
    const float* br     = (const float*)d_in[1];
    const float* bi     = (const float*)d_in[2];
    const float* rho    = (const float*)d_in[3];
    const float* h0     = (const float*)d_in[4];
    const float* c0     = (const float*)d_in[5];
    const float* Wihc   = (const float*)d_in[6];
    const float* Whhc   = (const float*)d_in[7];
    const float* bihc   = (const float*)d_in[8];
    const float* bhhc   = (const float*)d_in[9];
    const float* Wp     = (const float*)d_in[10];
    const float* bp     = (const float*)d_in[11];
    const float* Wih0   = (const float*)d_in[12];
    const float* Whh0   = (const float*)d_in[13];
    const float* bih0   = (const float*)d_in[14];
    const float* bhh0   = (const float*)d_in[15];
    const float* Whr0   = (const float*)d_in[16];
    const float* Wih1   = (const float*)d_in[17];
    const float* Whh1   = (const float*)d_in[18];
    const float* bih1   = (const float*)d_in[19];
    const float* bhh1   = (const float*)d_in[20];
    const float* Whr1   = (const float*)d_in[21];

    int B = in_sizes[0];
    int nblocks = B / BT;

    cudaFuncSetAttribute(fused_kernel,
                         cudaFuncAttributeMaxDynamicSharedMemorySize,
                         SMEM_BYTES);

    prep_kernel<<<128, 256>>>(Wihc, Whhc, bihc, bhhc, Wp,
                              Wih0, Whh0, bih0, bhh0, Whr0,
                              Wih1, Whh1, bih1, bhh1, Whr1);

    fused_kernel<<<nblocks, NTH, SMEM_BYTES>>>(
        meas, br, bi, rho, h0, c0, bp, (float*)d_out);
}

// round 8
// speedup vs baseline: 2.0803x; 1.2344x over previous
#include <cuda_runtime.h>

// ---------------------------------------------------------------------------
// Fused LSTMMeasurementPredictor — round 8: warp-specialized dual chains
//   B=131072, H=128, NQ=2, P=32, D_IN=17, T=16
// 512 threads / 32-batch tile. Warps 0-7 (group A): cell LSTM -> Wp ->
// physics -> x_{t+1}. Warps 8-15 (group B): lstm0 -> proj0 -> lstm1 -> proj1
// -> out. Chains are data-independent within a step (both read x_t); X is
// double-buffered. Group-local named barriers; ONE CTA barrier per step.
// Inner GEMM loop identical to R4 (compact weights, 32 FFMA2 per LDG.128).
// ---------------------------------------------------------------------------

#define NTH 512
#define BT  32
#define SS  36   // padded row stride; 36 mod 32 = 4 -> conflict-free LDS.128

constexpr int OFF_XA  = 0;                   // 17  rows : x ping
constexpr int OFF_XB  = OFF_XA  + 17  * SS;  // 17  rows : x pong
constexpr int OFF_HCA = OFF_XB  + 17  * SS;  // 128 rows : cell h ping
constexpr int OFF_HCB = OFF_HCA + 128 * SS;  // 128 rows : cell h pong
constexpr int OFF_S   = OFF_HCB + 128 * SS;  // 128 rows : group-B s staging
constexpr int OFF_CC  = OFF_S   + 128 * SS;  // 128 rows : cell c
constexpr int OFF_H0  = OFF_CC  + 128 * SS;  // 32  rows : lstm0 proj h
constexpr int OFF_C0  = OFF_H0  + 32  * SS;  // 128 rows : lstm0 c
constexpr int OFF_H1  = OFF_C0  + 128 * SS;  // 32  rows : lstm1 proj h
constexpr int OFF_C1  = OFF_H1  + 32  * SS;  // 128 rows : lstm1 c
constexpr int OFF_RHO = OFF_C1  + 128 * SS;  // 32*33    : rho
constexpr int OFF_V   = OFF_RHO + 32 * 33;   // 8 rows   : projector v
constexpr int SMEM_FLOATS = OFF_V + 8 * SS;
constexpr int SMEM_BYTES  = SMEM_FLOATS * 4; // ~130 KB -> ~98 KB left for L1

// compact packed weights: W[k][512], column jp = u*4 + gate (i,f,g,o).
// +1024 floats pad so the distance-2 prefetch can overshoot by 2 rows.
__device__ __align__(16) float g_Wc[145 * 512 + 1024];
__device__ __align__(16) float g_bc[512];
__device__ __align__(16) float g_W0[49 * 512 + 1024];
__device__ __align__(16) float g_b0[512];
__device__ __align__(16) float g_W1[64 * 512 + 1024];
__device__ __align__(16) float g_b1[512];
__device__ __align__(16) float g_Whr0T[128 * 32];   // [k][n] compact
__device__ __align__(16) float g_Whr1T[128 * 32];
__device__ __align__(16) float g_WpT[128 * 8];      // [k][n] compact

__global__ void prep_kernel(
    const float* __restrict__ Wihc, const float* __restrict__ Whhc,
    const float* __restrict__ bihc, const float* __restrict__ bhhc,
    const float* __restrict__ Wp,
    const float* __restrict__ Wih0, const float* __restrict__ Whh0,
    const float* __restrict__ bih0, const float* __restrict__ bhh0,
    const float* __restrict__ Whr0,
    const float* __restrict__ Wih1, const float* __restrict__ Whh1,
    const float* __restrict__ bih1, const float* __restrict__ bhh1,
    const float* __restrict__ Whr1)
{
    int i0 = blockIdx.x * blockDim.x + threadIdx.x;
    int stride = gridDim.x * blockDim.x;

    for (int i = i0; i < 145 * 512; i += stride) {
        int k = i >> 9, jp = i & 511;
        int u = jp >> 2, g = jp & 3, j = g * 128 + u;
        g_Wc[i] = (k < 17) ? Wihc[j * 17 + k] : Whhc[j * 128 + (k - 17)];
    }
    for (int i = i0; i < 49 * 512; i += stride) {
        int k = i >> 9, jp = i & 511;
        int u = jp >> 2, g = jp & 3, j = g * 128 + u;
        g_W0[i] = (k < 17) ? Wih0[j * 17 + k] : Whh0[j * 32 + (k - 17)];
    }
    for (int i = i0; i < 64 * 512; i += stride) {
        int k = i >> 9, jp = i & 511;
        int u = jp >> 2, g = jp & 3, j = g * 128 + u;
        g_W1[i] = (k < 32) ? Wih1[j * 32 + k] : Whh1[j * 32 + (k - 32)];
    }
    for (int i = i0; i < 1024; i += stride) {
        g_Wc[145 * 512 + i] = 0.f;
        g_W0[49 * 512 + i] = 0.f;
        g_W1[64 * 512 + i] = 0.f;
    }
    for (int i = i0; i < 512; i += stride) {
        int u = i >> 2, g = i & 3, j = g * 128 + u;
        g_bc[i] = bihc[j] + bhhc[j];
        g_b0[i] = bih0[j] + bhh0[j];
        g_b1[i] = bih1[j] + bhh1[j];
    }
    for (int i = i0; i < 128 * 32; i += stride) {
        int k = i >> 5, n = i & 31;
        g_Whr0T[i] = Whr0[n * 128 + k];
        g_Whr1T[i] = Whr1[n * 128 + k];
    }
    for (int i = i0; i < 128 * 8; i += stride) {
        int k = i >> 3, n = i & 7;
        g_WpT[i] = Wp[n * 128 + k];
    }
}

// ---------------------------------------------------------------------------
typedef unsigned long long ull;

__device__ __forceinline__ void fma2(ull& acc, ull a, ull b) {
    asm("fma.rn.f32x2 %0, %1, %2, %0;" : "+l"(acc) : "l"(a), "l"(b));
}
__device__ __forceinline__ ull dup2(float x) {
    ull r;
    asm("mov.b64 %0, {%1, %1};" : "=l"(r) : "f"(x));
    return r;
}
__device__ __forceinline__ void unpk(ull v, float& lo, float& hi) {
    asm("mov.b64 {%0, %1}, %2;" : "=f"(lo), "=f"(hi) : "l"(v));
}
#define BARA() asm volatile("bar.sync 1, 256;" ::: "memory")
#define BARB() asm volatile("bar.sync 2, 256;" ::: "memory")

__device__ __forceinline__ float fsig(float x) {
    return __fdividef(1.0f, 1.0f + __expf(-x));
}
__device__ __forceinline__ float ftanh(float x) {
    return __fdividef(2.0f, 1.0f + __expf(-2.0f * x)) - 1.0f;
}

// LSTM step: G[32,512] = [A(KA); B(KB)] @ W + bias, then gate update.
// 256-thread collective: unit u = gtid&127 (cols 4u..4u+3),
// batches b0 = (gtid>>7)*16 .. +15. acc[gate][pair] = 32 ull accs.
// R4 inner loop: 1 compact LDG.128 -> 4 dup MOVs -> 32 FFMA2 per k.
template <int KA, int KB>
__device__ __forceinline__ void lstm_step(
    const float* __restrict__ W, const float* __restrict__ bias,
    const float* shA, const float* shB, float* shC, float* shOut,
    int u, int b0)
{
    constexpr int K = KA + KB;
    ull acc[4][8];
    {
        float4 bs = *(const float4*)(bias + 4 * u);
        ull d0 = dup2(bs.x), d1 = dup2(bs.y), d2 = dup2(bs.z), d3 = dup2(bs.w);
#pragma unroll
        for (int p = 0; p < 8; ++p) {
            acc[0][p] = d0; acc[1][p] = d1; acc[2][p] = d2; acc[3][p] = d3;
        }
    }
    const float* Wu    = W + 4 * u;
    const float* baseA = shA + b0;
    const float* baseB = shB + b0 - KA * SS;

    float4 w0 = __ldg((const float4*)(Wu));
    float4 w1 = __ldg((const float4*)(Wu + 512));
#pragma unroll 4
    for (int k = 0; k < K; ++k) {
        float4 wn = __ldg((const float4*)(Wu + (k + 2) * 512));   // pad-safe
        const float* ap = (k < KA ? baseA : baseB) + k * SS;
        ull wd0 = dup2(w0.x), wd1 = dup2(w0.y), wd2 = dup2(w0.z), wd3 = dup2(w0.w);
#pragma unroll
        for (int c = 0; c < 4; ++c) {
            ulonglong2 a = *(const ulonglong2*)(ap + 4 * c);
            fma2(acc[0][2 * c], wd0, a.x); fma2(acc[0][2 * c + 1], wd0, a.y);
            fma2(acc[1][2 * c], wd1, a.x); fma2(acc[1][2 * c + 1], wd1, a.y);
            fma2(acc[2][2 * c], wd2, a.x); fma2(acc[2][2 * c + 1], wd2, a.y);
            fma2(acc[3][2 * c], wd3, a.x); fma2(acc[3][2 * c + 1], wd3, a.y);
        }
        w0 = w1; w1 = wn;
    }

    // epilogue: gates -> c update -> s (16 batches)
#pragma unroll
    for (int q = 0; q < 4; ++q) {
        int bq = b0 + 4 * q;
        float gi[4], gf[4], gg[4], go[4];
        unpk(acc[0][2 * q], gi[0], gi[1]); unpk(acc[0][2 * q + 1], gi[2], gi[3]);
        unpk(acc[1][2 * q], gf[0], gf[1]); unpk(acc[1][2 * q + 1], gf[2], gf[3]);
        unpk(acc[2][2 * q], gg[0], gg[1]); unpk(acc[2][2 * q + 1], gg[2], gg[3]);
        unpk(acc[3][2 * q], go[0], go[1]); unpk(acc[3][2 * q + 1], go[2], go[3]);
        float4 cv = *(const float4*)(shC + u * SS + bq);
        float cb[4] = {cv.x, cv.y, cv.z, cv.w};
        float sb[4];
#pragma unroll
        for (int j = 0; j < 4; ++j) {
            float cn = fsig(gf[j]) * cb[j] + fsig(gi[j]) * ftanh(gg[j]);
            cb[j] = cn;
            sb[j] = fsig(go[j]) * ftanh(cn);
        }
        *(float4*)(shC + u * SS + bq)   = make_float4(cb[0], cb[1], cb[2], cb[3]);
        *(float4*)(shOut + u * SS + bq) = make_float4(sb[0], sb[1], sb[2], sb[3]);
    }
}

// hp[32,32] = s[32,128] @ WhrT[128,32]. 256-thread collective:
// cg = gtid&7 -> cols 4cg..4cg+3, b = gtid>>3 (0..31).
__device__ __forceinline__ void proj_gemm(
    const float* __restrict__ WT, const float* shS, float* shHdst,
    float* outp, int gtid)
{
    const int cg = gtid & 7;
    const int b  = gtid >> 3;
    ull acc0 = 0ull, acc1 = 0ull;
    const float* Wu = WT + 4 * cg;
#pragma unroll 8
    for (int k = 0; k < 128; ++k) {
        ulonglong2 w = __ldg((const ulonglong2*)(Wu + k * 32));
        ull a = dup2(shS[k * SS + b]);
        fma2(acc0, w.x, a);
        fma2(acc1, w.y, a);
    }
    float v0, v1, v2, v3;
    unpk(acc0, v0, v1);
    unpk(acc1, v2, v3);
    shHdst[(4 * cg + 0) * SS + b] = v0;
    shHdst[(4 * cg + 1) * SS + b] = v1;
    shHdst[(4 * cg + 2) * SS + b] = v2;
    shHdst[(4 * cg + 3) * SS + b] = v3;
    if (outp) {
        *(float4*)(outp + (size_t)b * 512 + 4 * cg) = make_float4(v0, v1, v2, v3);
    }
}

// v[8,32] = h_new[32,128] @ WpT[128,8] + bp. 256-thread collective:
// nn = gtid>>5 (0..7), bb = gtid&31.
__device__ __forceinline__ void wp_gemm(
    const float* __restrict__ bp, const float* shS, float* shV, int gtid)
{
    int nn = gtid >> 5, bb = gtid & 31;
    float a = __ldg(&bp[nn]);
#pragma unroll 8
    for (int k = 0; k < 128; ++k)
        a += shS[k * SS + bb] * __ldg(&g_WpT[k * 8 + nn]);
    shV[nn * SS + bb] = a;
}

// quantum measurement physics for one batch element b (0..31); writes xnext
__device__ __forceinline__ void physics(const float* shV, const float* shRHO,
                                        float* shX, int b)
{
    float Mr[2][2][2], Mi[2][2][2];
#pragma unroll
    for (int q = 0; q < 2; ++q) {
        float ar = shV[(q * 4 + 0) * SS + b];
        float ai = shV[(q * 4 + 1) * SS + b];
        float br = shV[(q * 4 + 2) * SS + b];
        float bi = shV[(q * 4 + 3) * SS + b];
        float n00 = ar * ar + ai * ai;
        float n11 = br * br + bi * bi;
        float inv = 1.0f / (n00 + n11);
        float pr = (ar * br + ai * bi) * inv;
        float pi = (ai * br - ar * bi) * inv;
        Mr[q][0][0] = n00 * inv; Mi[q][0][0] = 0.f;
        Mr[q][0][1] = pr;        Mi[q][0][1] = pi;
        Mr[q][1][0] = pr;        Mi[q][1][0] = -pi;
        Mr[q][1][1] = n11 * inv; Mi[q][1][1] = 0.f;
    }
    const float* rp = shRHO + b * 33;
    float m = 0.f;
#pragma unroll
    for (int a = 0; a < 2; ++a)
#pragma unroll
        for (int c = 0; c < 2; ++c)
#pragma unroll
            for (int b2 = 0; b2 < 2; ++b2)
#pragma unroll
                for (int d = 0; d < 2; ++d) {
                    float tr_ = Mr[0][a][c] * Mr[1][b2][d] - Mi[0][a][c] * Mi[1][b2][d];
                    float ti_ = Mr[0][a][c] * Mi[1][b2][d] + Mi[0][a][c] * Mr[1][b2][d];
                    int row = c * 2 + d, col = a * 2 + b2;
                    float rr = rp[row * 4 + col];
                    float ri = rp[16 + row * 4 + col];
                    m += tr_ * rr - ti_ * ri;
                }
    shX[0 * SS + b] = m;
#pragma unroll
    for (int q = 0; q < 2; ++q)
#pragma unroll
        for (int i = 0; i < 2; ++i)
#pragma unroll
            for (int j = 0; j < 2; ++j) {
                int base = 1 + 8 * q + 4 * i + 2 * j;
                shX[base * SS + b]       = Mr[q][i][j];
                shX[(base + 1) * SS + b] = Mi[q][i][j];
            }
}

__global__ void __launch_bounds__(NTH, 1) fused_kernel(
    const float* __restrict__ meas, const float* __restrict__ basis_r,
    const float* __restrict__ basis_i, const float* __restrict__ rho,
    const float* __restrict__ h0in, const float* __restrict__ c0in,
    const float* __restrict__ bp, float* __restrict__ out)
{
    extern __shared__ float sm[];
    float* shS   = sm + OFF_S;
    float* shCC  = sm + OFF_CC;
    float* shH0  = sm + OFF_H0;
    float* shC0  = sm + OFF_C0;
    float* shH1  = sm + OFF_H1;
    float* shC1  = sm + OFF_C1;
    float* shRHO = sm + OFF_RHO;
    float* shV   = sm + OFF_V;

    const int tid = threadIdx.x;
    const int b0g = blockIdx.x * BT;

    // ---- init loads into XA ----
    for (int i = tid; i < BT; i += NTH)
        sm[OFF_XA + 0 * SS + i] = meas[b0g + i];
    for (int i = tid; i < BT * 8; i += NTH) {
        int b = i >> 3, e = i & 7;
        sm[OFF_XA + (1 + 2 * e) * SS + b] = basis_r[(size_t)(b0g + b) * 8 + e];
        sm[OFF_XA + (2 + 2 * e) * SS + b] = basis_i[(size_t)(b0g + b) * 8 + e];
    }
    for (int i = tid; i < BT * 32; i += NTH) {
        int b = i >> 5, e = i & 31;
        shRHO[b * 33 + e] = rho[(size_t)(b0g + b) * 32 + e];
    }
    for (int i = tid; i < BT * 128; i += NTH) {
        int b = i >> 7, u = i & 127;
        sm[OFF_HCA + u * SS + b] = h0in[(size_t)(b0g + b) * 128 + u];
        shCC[u * SS + b]         = c0in[(size_t)(b0g + b) * 128 + u];
    }
    // zero H0, C0, H1, C1 (320 contiguous rows)
    for (int i = tid; i < 320 * SS; i += NTH)
        sm[OFF_H0 + i] = 0.f;
    __syncthreads();

    const bool isA = (tid < 256);
    const int gtid = tid & 255;
    const int u  = gtid & 127;
    const int b0 = (gtid >> 7) * 16;

    float* xcur = sm + OFF_XA;
    float* xnxt = sm + OFF_XB;
    float* hcur = sm + OFF_HCA;
    float* hnxt = sm + OFF_HCB;

    for (int t = 0; t < 16; ++t) {
        if (isA) {
            // group A: cell chain (produces x_{t+1} into xnxt, h_new into hnxt)
            if (t < 15) {
                lstm_step<17, 128>(g_Wc, g_bc, xcur, hcur, shCC, hnxt, u, b0);
                BARA();
                wp_gemm(bp, hnxt, shV, gtid);
                BARA();
                if (gtid < BT) physics(shV, shRHO, xnxt, gtid);
            }
        } else {
            // group B: output chain for step t (reads xcur only)
            lstm_step<17, 32>(g_W0, g_b0, xcur, shH0, shC0, shS, u, b0);
            BARB();
            proj_gemm(g_Whr0T, shS, shH0, nullptr, gtid);
            BARB();
            lstm_step<32, 32>(g_W1, g_b1, shH0, shH1, shC1, shS, u, b0);
            BARB();
            proj_gemm(g_Whr1T, shS, shH1,
                      out + (size_t)b0g * 512 + (size_t)t * 32, gtid);
        }
        __syncthreads();
        if (t < 15) {
            float* tp = hcur; hcur = hnxt; hnxt = tp;
            float* tx = xcur; xcur = xnxt; xnxt = tx;
        }
    }
}

extern "C" void kernel_launch(void* const* d_in, const int* in_sizes, int n_in,
                              void* d_out, int out_size)
{
    const float* meas   = (const float*)d_in[0];
    const float* br     = (const float*)d_in[1];
    const float* bi     = (const float*)d_in[2];
    const float* rho    = (const float*)d_in[3];
    const float* h0     = (const float*)d_in[4];
    const float* c0     = (const float*)d_in[5];
    const float* Wihc   = (const float*)d_in[6];
    const float* Whhc   = (const float*)d_in[7];
    const float* bihc   = (const float*)d_in[8];
    const float* bhhc   = (const float*)d_in[9];
    const float* Wp     = (const float*)d_in[10];
    const float* bp     = (const float*)d_in[11];
    const float* Wih0   = (const float*)d_in[12];
    const float* Whh0   = (const float*)d_in[13];
    const float* bih0   = (const float*)d_in[14];
    const float* bhh0   = (const float*)d_in[15];
    const float* Whr0   = (const float*)d_in[16];
    const float* Wih1   = (const float*)d_in[17];
    const float* Whh1   = (const float*)d_in[18];
    const float* bih1   = (const float*)d_in[19];
    const float* bhh1   = (const float*)d_in[20];
    const float* Whr1   = (const float*)d_in[21];

    int B = in_sizes[0];
    int nblocks = B / BT;

    cudaFuncSetAttribute(fused_kernel,
                         cudaFuncAttributeMaxDynamicSharedMemorySize,
                         SMEM_BYTES);

    prep_kernel<<<128, 256>>>(Wihc, Whhc, bihc, bhhc, Wp,
                              Wih0, Whh0, bih0, bhh0, Whr0,
                              Wih1, Whh1, bih1, bhh1, Whr1);

    fused_kernel<<<nblocks, NTH, SMEM_BYTES>>>(
        meas, br, bi, rho, h0, c0, bp, (float*)d_out);
}

// round 9
// speedup vs baseline: 2.0983x; 1.0086x over previous
#include <cuda_runtime.h>

// ---------------------------------------------------------------------------
// Fused LSTMMeasurementPredictor — round 9
//   B=131072, H=128, NQ=2, P=32, D_IN=17, T=16
// 512 threads / 32-batch tile, warp-specialized (R8 structure):
//   group A (warps 0-7):  cell LSTM -> Wp -> physics -> x_{t+1}
//   group B (warps 8-15): lstm0 -> proj0 -> lstm1 -> proj1 -> out
// NEW: proj0/proj1/wp weights pinned in SMEM in duplicated-pair form
// (copied once per CTA) -> their inner loops are pure LDS+FFMA2 with no
// L2-latency LDG chains and no dup-MOVs. lstm GEMM inner loop = R4 shape.
// ---------------------------------------------------------------------------

#define NTH 512
#define BT  32
#define SS  36   // padded row stride; (36*4)%16==0, conflict-free LDS.128

constexpr int OFF_XA  = 0;                   // 17  rows : x ping
constexpr int OFF_XB  = OFF_XA  + 17  * SS;  // 17  rows : x pong
constexpr int OFF_HCA = OFF_XB  + 17  * SS;  // 128 rows : cell h ping
constexpr int OFF_HCB = OFF_HCA + 128 * SS;  // 128 rows : cell h pong
constexpr int OFF_S   = OFF_HCB + 128 * SS;  // 128 rows : group-B s staging
constexpr int OFF_CC  = OFF_S   + 128 * SS;  // 128 rows : cell c
constexpr int OFF_H0  = OFF_CC  + 128 * SS;  // 32  rows : lstm0 proj h
constexpr int OFF_C0  = OFF_H0  + 32  * SS;  // 128 rows : lstm0 c
constexpr int OFF_H1  = OFF_C0  + 128 * SS;  // 32  rows : lstm1 proj h
constexpr int OFF_C1  = OFF_H1  + 32  * SS;  // 128 rows : lstm1 c
constexpr int OFF_RHO = OFF_C1  + 128 * SS;  // 32*33    : rho
constexpr int OFF_V   = OFF_RHO + 32 * 33;   // 8 rows   : projector v
// duplicated-pair small-GEMM weights (filled once per CTA):
constexpr int OFF_PW0 = OFF_V   + 8 * SS;    // 128*64 : Whr0T dup'd
constexpr int OFF_PW1 = OFF_PW0 + 128 * 64;  // 128*64 : Whr1T dup'd
constexpr int OFF_PWP = OFF_PW1 + 128 * 64;  // 128*16 : WpT dup'd
constexpr int SMEM_FLOATS = OFF_PWP + 128 * 16;
constexpr int SMEM_BYTES  = SMEM_FLOATS * 4; // ~199 KB

// compact packed weights: W[k][512], column jp = u*4 + gate (i,f,g,o).
// +1024 floats pad so the distance-2 prefetch can overshoot by 2 rows.
__device__ __align__(16) float g_Wc[145 * 512 + 1024];
__device__ __align__(16) float g_bc[512];
__device__ __align__(16) float g_W0[49 * 512 + 1024];
__device__ __align__(16) float g_b0[512];
__device__ __align__(16) float g_W1[64 * 512 + 1024];
__device__ __align__(16) float g_b1[512];
__device__ __align__(16) float g_Whr0T[128 * 32];   // [k][n] compact
__device__ __align__(16) float g_Whr1T[128 * 32];
__device__ __align__(16) float g_WpT[128 * 8];      // [k][n] compact

__global__ void prep_kernel(
    const float* __restrict__ Wihc, const float* __restrict__ Whhc,
    const float* __restrict__ bihc, const float* __restrict__ bhhc,
    const float* __restrict__ Wp,
    const float* __restrict__ Wih0, const float* __restrict__ Whh0,
    const float* __restrict__ bih0, const float* __restrict__ bhh0,
    const float* __restrict__ Whr0,
    const float* __restrict__ Wih1, const float* __restrict__ Whh1,
    const float* __restrict__ bih1, const float* __restrict__ bhh1,
    const float* __restrict__ Whr1)
{
    int i0 = blockIdx.x * blockDim.x + threadIdx.x;
    int stride = gridDim.x * blockDim.x;

    for (int i = i0; i < 145 * 512; i += stride) {
        int k = i >> 9, jp = i & 511;
        int u = jp >> 2, g = jp & 3, j = g * 128 + u;
        g_Wc[i] = (k < 17) ? Wihc[j * 17 + k] : Whhc[j * 128 + (k - 17)];
    }
    for (int i = i0; i < 49 * 512; i += stride) {
        int k = i >> 9, jp = i & 511;
        int u = jp >> 2, g = jp & 3, j = g * 128 + u;
        g_W0[i] = (k < 17) ? Wih0[j * 17 + k] : Whh0[j * 32 + (k - 17)];
    }
    for (int i = i0; i < 64 * 512; i += stride) {
        int k = i >> 9, jp = i & 511;
        int u = jp >> 2, g = jp & 3, j = g * 128 + u;
        g_W1[i] = (k < 32) ? Wih1[j * 32 + k] : Whh1[j * 32 + (k - 32)];
    }
    for (int i = i0; i < 1024; i += stride) {
        g_Wc[145 * 512 + i] = 0.f;
        g_W0[49 * 512 + i] = 0.f;
        g_W1[64 * 512 + i] = 0.f;
    }
    for (int i = i0; i < 512; i += stride) {
        int u = i >> 2, g = i & 3, j = g * 128 + u;
        g_bc[i] = bihc[j] + bhhc[j];
        g_b0[i] = bih0[j] + bhh0[j];
        g_b1[i] = bih1[j] + bhh1[j];
    }
    for (int i = i0; i < 128 * 32; i += stride) {
        int k = i >> 5, n = i & 31;
        g_Whr0T[i] = Whr0[n * 128 + k];
        g_Whr1T[i] = Whr1[n * 128 + k];
    }
    for (int i = i0; i < 128 * 8; i += stride) {
        int k = i >> 3, n = i & 7;
        g_WpT[i] = Wp[n * 128 + k];
    }
}

// ---------------------------------------------------------------------------
typedef unsigned long long ull;

__device__ __forceinline__ void fma2(ull& acc, ull a, ull b) {
    asm("fma.rn.f32x2 %0, %1, %2, %0;" : "+l"(acc) : "l"(a), "l"(b));
}
__device__ __forceinline__ ull dup2(float x) {
    ull r;
    asm("mov.b64 %0, {%1, %1};" : "=l"(r) : "f"(x));
    return r;
}
__device__ __forceinline__ void unpk(ull v, float& lo, float& hi) {
    asm("mov.b64 {%0, %1}, %2;" : "=f"(lo), "=f"(hi) : "l"(v));
}
#define BARA() asm volatile("bar.sync 1, 256;" ::: "memory")
#define BARB() asm volatile("bar.sync 2, 256;" ::: "memory")

__device__ __forceinline__ float fsig(float x) {
    return __fdividef(1.0f, 1.0f + __expf(-x));
}
__device__ __forceinline__ float ftanh(float x) {
    return __fdividef(2.0f, 1.0f + __expf(-2.0f * x)) - 1.0f;
}

// LSTM step: G[32,512] = [A(KA); B(KB)] @ W + bias, then gate update.
// 256-thread collective: unit u = gtid&127 (cols 4u..4u+3),
// batches b0 = (gtid>>7)*16 .. +15. acc[gate][pair] = 32 ull accs.
// R4 inner loop: 1 compact LDG.128 -> 4 dup MOVs -> 32 FFMA2 per k.
template <int KA, int KB>
__device__ __forceinline__ void lstm_step(
    const float* __restrict__ W, const float* __restrict__ bias,
    const float* shA, const float* shB, float* shC, float* shOut,
    int u, int b0)
{
    constexpr int K = KA + KB;
    ull acc[4][8];
    {
        float4 bs = *(const float4*)(bias + 4 * u);
        ull d0 = dup2(bs.x), d1 = dup2(bs.y), d2 = dup2(bs.z), d3 = dup2(bs.w);
#pragma unroll
        for (int p = 0; p < 8; ++p) {
            acc[0][p] = d0; acc[1][p] = d1; acc[2][p] = d2; acc[3][p] = d3;
        }
    }
    const float* Wu    = W + 4 * u;
    const float* baseA = shA + b0;
    const float* baseB = shB + b0 - KA * SS;

    float4 w0 = __ldg((const float4*)(Wu));
    float4 w1 = __ldg((const float4*)(Wu + 512));
#pragma unroll 4
    for (int k = 0; k < K; ++k) {
        float4 wn = __ldg((const float4*)(Wu + (k + 2) * 512));   // pad-safe
        const float* ap = (k < KA ? baseA : baseB) + k * SS;
        ull wd0 = dup2(w0.x), wd1 = dup2(w0.y), wd2 = dup2(w0.z), wd3 = dup2(w0.w);
#pragma unroll
        for (int c = 0; c < 4; ++c) {
            ulonglong2 a = *(const ulonglong2*)(ap + 4 * c);
            fma2(acc[0][2 * c], wd0, a.x); fma2(acc[0][2 * c + 1], wd0, a.y);
            fma2(acc[1][2 * c], wd1, a.x); fma2(acc[1][2 * c + 1], wd1, a.y);
            fma2(acc[2][2 * c], wd2, a.x); fma2(acc[2][2 * c + 1], wd2, a.y);
            fma2(acc[3][2 * c], wd3, a.x); fma2(acc[3][2 * c + 1], wd3, a.y);
        }
        w0 = w1; w1 = wn;
    }

    // epilogue: gates -> c update -> s (16 batches)
#pragma unroll
    for (int q = 0; q < 4; ++q) {
        int bq = b0 + 4 * q;
        float gi[4], gf[4], gg[4], go[4];
        unpk(acc[0][2 * q], gi[0], gi[1]); unpk(acc[0][2 * q + 1], gi[2], gi[3]);
        unpk(acc[1][2 * q], gf[0], gf[1]); unpk(acc[1][2 * q + 1], gf[2], gf[3]);
        unpk(acc[2][2 * q], gg[0], gg[1]); unpk(acc[2][2 * q + 1], gg[2], gg[3]);
        unpk(acc[3][2 * q], go[0], go[1]); unpk(acc[3][2 * q + 1], go[2], go[3]);
        float4 cv = *(const float4*)(shC + u * SS + bq);
        float cb[4] = {cv.x, cv.y, cv.z, cv.w};
        float sb[4];
#pragma unroll
        for (int j = 0; j < 4; ++j) {
            float cn = fsig(gf[j]) * cb[j] + fsig(gi[j]) * ftanh(gg[j]);
            cb[j] = cn;
            sb[j] = fsig(go[j]) * ftanh(cn);
        }
        *(float4*)(shC + u * SS + bq)   = make_float4(cb[0], cb[1], cb[2], cb[3]);
        *(float4*)(shOut + u * SS + bq) = make_float4(sb[0], sb[1], sb[2], sb[3]);
    }
}

// hp[32,32] = s[32,128] @ WhrT[128,32], weights dup'd in SMEM (stride 64).
// 256-thread collective: cg = gtid&15 -> cols 2cg,2cg+1;
// p = gtid>>4 -> batches 2p, 2p+1. Pure LDS + FFMA2, zero LDG / MOV.
__device__ __forceinline__ void proj_gemm(
    const float* sPW, const float* shS, float* shHdst,
    float* outp, int gtid)
{
    const int cg = gtid & 15;
    const int p  = gtid >> 4;
    ull acc0 = 0ull, acc1 = 0ull;
    const float* Wu = sPW + 4 * cg;
#pragma unroll 8
    for (int k = 0; k < 128; ++k) {
        ulonglong2 w = *(const ulonglong2*)(Wu + k * 64);  // (wc0,wc0),(wc1,wc1)
        ull a = *(const ull*)(shS + k * SS + 2 * p);       // (s_b0, s_b1)
        fma2(acc0, w.x, a);
        fma2(acc1, w.y, a);
    }
    float v00, v10, v01, v11;   // v[b][c]
    unpk(acc0, v00, v10);
    unpk(acc1, v01, v11);
    float* hp = shHdst + (2 * cg) * SS + 2 * p;
    hp[0] = v00; hp[1] = v10;
    hp[SS] = v01; hp[SS + 1] = v11;
    if (outp) {
        *(float2*)(outp + (size_t)(2 * p) * 512 + 2 * cg)     = make_float2(v00, v01);
        *(float2*)(outp + (size_t)(2 * p + 1) * 512 + 2 * cg) = make_float2(v10, v11);
    }
}

// v[8,32] = h_new[32,128] @ WpT[128,8] + bp, weights dup'd in SMEM (stride 16).
// 128 active threads: nn = gtid&7 (one col), p = gtid>>3 (batches 2p,2p+1).
__device__ __forceinline__ void wp_gemm(
    const float* __restrict__ bp, const float* sPWP,
    const float* shS, float* shV, int gtid)
{
    if (gtid >= 128) return;
    const int nn = gtid & 7;
    const int p  = gtid >> 3;
    ull acc = dup2(__ldg(&bp[nn]));
    const float* Wu = sPWP + 2 * nn;
#pragma unroll 8
    for (int k = 0; k < 128; ++k) {
        ull w = *(const ull*)(Wu + k * 16);
        ull a = *(const ull*)(shS + k * SS + 2 * p);
        fma2(acc, w, a);
    }
    float lo, hi;
    unpk(acc, lo, hi);
    shV[nn * SS + 2 * p]     = lo;
    shV[nn * SS + 2 * p + 1] = hi;
}

// quantum measurement physics for one batch element b (0..31); writes xnext
__device__ __forceinline__ void physics(const float* shV, const float* shRHO,
                                        float* shX, int b)
{
    float Mr[2][2][2], Mi[2][2][2];
#pragma unroll
    for (int q = 0; q < 2; ++q) {
        float ar = shV[(q * 4 + 0) * SS + b];
        float ai = shV[(q * 4 + 1) * SS + b];
        float br = shV[(q * 4 + 2) * SS + b];
        float bi = shV[(q * 4 + 3) * SS + b];
        float n00 = ar * ar + ai * ai;
        float n11 = br * br + bi * bi;
        float inv = 1.0f / (n00 + n11);
        float pr = (ar * br + ai * bi) * inv;
        float pi = (ai * br - ar * bi) * inv;
        Mr[q][0][0] = n00 * inv; Mi[q][0][0] = 0.f;
        Mr[q][0][1] = pr;        Mi[q][0][1] = pi;
        Mr[q][1][0] = pr;        Mi[q][1][0] = -pi;
        Mr[q][1][1] = n11 * inv; Mi[q][1][1] = 0.f;
    }
    const float* rp = shRHO + b * 33;
    float m = 0.f;
#pragma unroll
    for (int a = 0; a < 2; ++a)
#pragma unroll
        for (int c = 0; c < 2; ++c)
#pragma unroll
            for (int b2 = 0; b2 < 2; ++b2)
#pragma unroll
                for (int d = 0; d < 2; ++d) {
                    float tr_ = Mr[0][a][c] * Mr[1][b2][d] - Mi[0][a][c] * Mi[1][b2][d];
                    float ti_ = Mr[0][a][c] * Mi[1][b2][d] + Mi[0][a][c] * Mr[1][b2][d];
                    int row = c * 2 + d, col = a * 2 + b2;
                    float rr = rp[row * 4 + col];
                    float ri = rp[16 + row * 4 + col];
                    m += tr_ * rr - ti_ * ri;
                }
    shX[0 * SS + b] = m;
#pragma unroll
    for (int q = 0; q < 2; ++q)
#pragma unroll
        for (int i = 0; i < 2; ++i)
#pragma unroll
            for (int j = 0; j < 2; ++j) {
                int base = 1 + 8 * q + 4 * i + 2 * j;
                shX[base * SS + b]       = Mr[q][i][j];
                shX[(base + 1) * SS + b] = Mi[q][i][j];
            }
}

__global__ void __launch_bounds__(NTH, 1) fused_kernel(
    const float* __restrict__ meas, const float* __restrict__ basis_r,
    const float* __restrict__ basis_i, const float* __restrict__ rho,
    const float* __restrict__ h0in, const float* __restrict__ c0in,
    const float* __restrict__ bp, float* __restrict__ out)
{
    extern __shared__ float sm[];
    float* shS   = sm + OFF_S;
    float* shCC  = sm + OFF_CC;
    float* shH0  = sm + OFF_H0;
    float* shC0  = sm + OFF_C0;
    float* shH1  = sm + OFF_H1;
    float* shC1  = sm + OFF_C1;
    float* shRHO = sm + OFF_RHO;
    float* shV   = sm + OFF_V;
    float* sPW0  = sm + OFF_PW0;
    float* sPW1  = sm + OFF_PW1;
    float* sPWP  = sm + OFF_PWP;

    const int tid = threadIdx.x;
    const int b0g = blockIdx.x * BT;

    // ---- init loads into XA ----
    for (int i = tid; i < BT; i += NTH)
        sm[OFF_XA + 0 * SS + i] = meas[b0g + i];
    for (int i = tid; i < BT * 8; i += NTH) {
        int b = i >> 3, e = i & 7;
        sm[OFF_XA + (1 + 2 * e) * SS + b] = basis_r[(size_t)(b0g + b) * 8 + e];
        sm[OFF_XA + (2 + 2 * e) * SS + b] = basis_i[(size_t)(b0g + b) * 8 + e];
    }
    for (int i = tid; i < BT * 32; i += NTH) {
        int b = i >> 5, e = i & 31;
        shRHO[b * 33 + e] = rho[(size_t)(b0g + b) * 32 + e];
    }
    for (int i = tid; i < BT * 128; i += NTH) {
        int b = i >> 7, u = i & 127;
        sm[OFF_HCA + u * SS + b] = h0in[(size_t)(b0g + b) * 128 + u];
        shCC[u * SS + b]         = c0in[(size_t)(b0g + b) * 128 + u];
    }
    // zero H0, C0, H1, C1 (320 contiguous rows)
    for (int i = tid; i < 320 * SS; i += NTH)
        sm[OFF_H0 + i] = 0.f;
    // fill dup'd small-GEMM weights (once per CTA)
    for (int i = tid; i < 128 * 32; i += NTH) {
        int k = i >> 5, n = i & 31;
        float v0 = __ldg(&g_Whr0T[i]);
        float v1 = __ldg(&g_Whr1T[i]);
        sPW0[k * 64 + 2 * n] = v0; sPW0[k * 64 + 2 * n + 1] = v0;
        sPW1[k * 64 + 2 * n] = v1; sPW1[k * 64 + 2 * n + 1] = v1;
    }
    for (int i = tid; i < 128 * 8; i += NTH) {
        int k = i >> 3, n = i & 7;
        float v = __ldg(&g_WpT[i]);
        sPWP[k * 16 + 2 * n] = v; sPWP[k * 16 + 2 * n + 1] = v;
    }
    __syncthreads();

    const bool isA = (tid < 256);
    const int gtid = tid & 255;
    const int u  = gtid & 127;
    const int b0 = (gtid >> 7) * 16;

    float* xcur = sm + OFF_XA;
    float* xnxt = sm + OFF_XB;
    float* hcur = sm + OFF_HCA;
    float* hnxt = sm + OFF_HCB;

    for (int t = 0; t < 16; ++t) {
        if (isA) {
            // group A: cell chain (produces x_{t+1} into xnxt, h_new into hnxt)
            if (t < 15) {
                lstm_step<17, 128>(g_Wc, g_bc, xcur, hcur, shCC, hnxt, u, b0);
                BARA();
                wp_gemm(bp, sPWP, hnxt, shV, gtid);
                BARA();
                if (gtid < BT) physics(shV, shRHO, xnxt, gtid);
            }
        } else {
            // group B: output chain for step t (reads xcur only)
            lstm_step<17, 32>(g_W0, g_b0, xcur, shH0, shC0, shS, u, b0);
            BARB();
            proj_gemm(sPW0, shS, shH0, nullptr, gtid);
            BARB();
            lstm_step<32, 32>(g_W1, g_b1, shH0, shH1, shC1, shS, u, b0);
            BARB();
            proj_gemm(sPW1, shS, shH1,
                      out + (size_t)b0g * 512 + (size_t)t * 32, gtid);
        }
        __syncthreads();
        if (t < 15) {
            float* tp = hcur; hcur = hnxt; hnxt = tp;
            float* tx = xcur; xcur = xnxt; xnxt = tx;
        }
    }
}

extern "C" void kernel_launch(void* const* d_in, const int* in_sizes, int n_in,
                              void* d_out, int out_size)
{
    const float* meas   = (const float*)d_in[0];
    const float* br     = (const float*)d_in[1];
    const float* bi     = (const float*)d_in[2];
    const float* rho    = (const float*)d_in[3];
    const float* h0     = (const float*)d_in[4];
    const float* c0     = (const float*)d_in[5];
    const float* Wihc   = (const float*)d_in[6];
    const float* Whhc   = (const float*)d_in[7];
    const float* bihc   = (const float*)d_in[8];
    const float* bhhc   = (const float*)d_in[9];
    const float* Wp     = (const float*)d_in[10];
    const float* bp     = (const float*)d_in[11];
    const float* Wih0   = (const float*)d_in[12];
    const float* Whh0   = (const float*)d_in[13];
    const float* bih0   = (const float*)d_in[14];
    const float* bhh0   = (const float*)d_in[15];
    const float* Whr0   = (const float*)d_in[16];
    const float* Wih1   = (const float*)d_in[17];
    const float* Whh1   = (const float*)d_in[18];
    const float* bih1   = (const float*)d_in[19];
    const float* bhh1   = (const float*)d_in[20];
    const float* Whr1   = (const float*)d_in[21];

    int B = in_sizes[0];
    int nblocks = B / BT;

    cudaFuncSetAttribute(fused_kernel,
                         cudaFuncAttributeMaxDynamicSharedMemorySize,
                         SMEM_BYTES);

    prep_kernel<<<128, 256>>>(Wihc, Whhc, bihc, bhhc, Wp,
                              Wih0, Whh0, bih0, bhh0, Whr0,
                              Wih1, Whh1, bih1, bhh1, Whr1);

    fused_kernel<<<nblocks, NTH, SMEM_BYTES>>>(
        meas, br, bi, rho, h0, c0, bp, (float*)d_out);
}

// round 10
// speedup vs baseline: 2.1485x; 1.0240x over previous
#include <cuda_runtime.h>

// ---------------------------------------------------------------------------
// Fused LSTMMeasurementPredictor — round 10
//   B=131072, H=128, NQ=2, P=32, D_IN=17, T=16
// R9 structure (warp-specialized dual chains, smem-pinned small-GEMM weights)
// + NEW: activation LDS prefetch (distance 1) in lstm_step, so each k-iter's
// 32 FFMA2 never wait on same-iteration shared loads. Weight LDG stays at
// prefetch distance 2.
// ---------------------------------------------------------------------------

#define NTH 512
#define BT  32
#define SS  36   // padded row stride; (36*4)%16==0, conflict-free LDS.128

constexpr int OFF_XA  = 0;                   // 17  rows : x ping
constexpr int OFF_XB  = OFF_XA  + 17  * SS;  // 17  rows : x pong
constexpr int OFF_HCA = OFF_XB  + 17  * SS;  // 128 rows : cell h ping
constexpr int OFF_HCB = OFF_HCA + 128 * SS;  // 128 rows : cell h pong
constexpr int OFF_S   = OFF_HCB + 128 * SS;  // 128 rows : group-B s staging
constexpr int OFF_CC  = OFF_S   + 128 * SS;  // 128 rows : cell c
constexpr int OFF_H0  = OFF_CC  + 128 * SS;  // 32  rows : lstm0 proj h
constexpr int OFF_C0  = OFF_H0  + 32  * SS;  // 128 rows : lstm0 c
constexpr int OFF_H1  = OFF_C0  + 128 * SS;  // 32  rows : lstm1 proj h
constexpr int OFF_C1  = OFF_H1  + 32  * SS;  // 128 rows : lstm1 c
constexpr int OFF_RHO = OFF_C1  + 128 * SS;  // 32*33    : rho
constexpr int OFF_V   = OFF_RHO + 32 * 33;   // 8 rows   : projector v
// duplicated-pair small-GEMM weights (filled once per CTA):
constexpr int OFF_PW0 = OFF_V   + 8 * SS;    // 128*64 : Whr0T dup'd
constexpr int OFF_PW1 = OFF_PW0 + 128 * 64;  // 128*64 : Whr1T dup'd
constexpr int OFF_PWP = OFF_PW1 + 128 * 64;  // 128*16 : WpT dup'd
constexpr int SMEM_FLOATS = OFF_PWP + 128 * 16;
constexpr int SMEM_BYTES  = SMEM_FLOATS * 4; // ~199 KB

// compact packed weights: W[k][512], column jp = u*4 + gate (i,f,g,o).
// +1024 floats pad so the distance-2 prefetch can overshoot by 2 rows.
__device__ __align__(16) float g_Wc[145 * 512 + 1024];
__device__ __align__(16) float g_bc[512];
__device__ __align__(16) float g_W0[49 * 512 + 1024];
__device__ __align__(16) float g_b0[512];
__device__ __align__(16) float g_W1[64 * 512 + 1024];
__device__ __align__(16) float g_b1[512];
__device__ __align__(16) float g_Whr0T[128 * 32];   // [k][n] compact
__device__ __align__(16) float g_Whr1T[128 * 32];
__device__ __align__(16) float g_WpT[128 * 8];      // [k][n] compact

__global__ void prep_kernel(
    const float* __restrict__ Wihc, const float* __restrict__ Whhc,
    const float* __restrict__ bihc, const float* __restrict__ bhhc,
    const float* __restrict__ Wp,
    const float* __restrict__ Wih0, const float* __restrict__ Whh0,
    const float* __restrict__ bih0, const float* __restrict__ bhh0,
    const float* __restrict__ Whr0,
    const float* __restrict__ Wih1, const float* __restrict__ Whh1,
    const float* __restrict__ bih1, const float* __restrict__ bhh1,
    const float* __restrict__ Whr1)
{
    int i0 = blockIdx.x * blockDim.x + threadIdx.x;
    int stride = gridDim.x * blockDim.x;

    for (int i = i0; i < 145 * 512; i += stride) {
        int k = i >> 9, jp = i & 511;
        int u = jp >> 2, g = jp & 3, j = g * 128 + u;
        g_Wc[i] = (k < 17) ? Wihc[j * 17 + k] : Whhc[j * 128 + (k - 17)];
    }
    for (int i = i0; i < 49 * 512; i += stride) {
        int k = i >> 9, jp = i & 511;
        int u = jp >> 2, g = jp & 3, j = g * 128 + u;
        g_W0[i] = (k < 17) ? Wih0[j * 17 + k] : Whh0[j * 32 + (k - 17)];
    }
    for (int i = i0; i < 64 * 512; i += stride) {
        int k = i >> 9, jp = i & 511;
        int u = jp >> 2, g = jp & 3, j = g * 128 + u;
        g_W1[i] = (k < 32) ? Wih1[j * 32 + k] : Whh1[j * 32 + (k - 32)];
    }
    for (int i = i0; i < 1024; i += stride) {
        g_Wc[145 * 512 + i] = 0.f;
        g_W0[49 * 512 + i] = 0.f;
        g_W1[64 * 512 + i] = 0.f;
    }
    for (int i = i0; i < 512; i += stride) {
        int u = i >> 2, g = i & 3, j = g * 128 + u;
        g_bc[i] = bihc[j] + bhhc[j];
        g_b0[i] = bih0[j] + bhh0[j];
        g_b1[i] = bih1[j] + bhh1[j];
    }
    for (int i = i0; i < 128 * 32; i += stride) {
        int k = i >> 5, n = i & 31;
        g_Whr0T[i] = Whr0[n * 128 + k];
        g_Whr1T[i] = Whr1[n * 128 + k];
    }
    for (int i = i0; i < 128 * 8; i += stride) {
        int k = i >> 3, n = i & 7;
        g_WpT[i] = Wp[n * 128 + k];
    }
}

// ---------------------------------------------------------------------------
typedef unsigned long long ull;

__device__ __forceinline__ void fma2(ull& acc, ull a, ull b) {
    asm("fma.rn.f32x2 %0, %1, %2, %0;" : "+l"(acc) : "l"(a), "l"(b));
}
__device__ __forceinline__ ull dup2(float x) {
    ull r;
    asm("mov.b64 %0, {%1, %1};" : "=l"(r) : "f"(x));
    return r;
}
__device__ __forceinline__ void unpk(ull v, float& lo, float& hi) {
    asm("mov.b64 {%0, %1}, %2;" : "=f"(lo), "=f"(hi) : "l"(v));
}
#define BARA() asm volatile("bar.sync 1, 256;" ::: "memory")
#define BARB() asm volatile("bar.sync 2, 256;" ::: "memory")

__device__ __forceinline__ float fsig(float x) {
    return __fdividef(1.0f, 1.0f + __expf(-x));
}
__device__ __forceinline__ float ftanh(float x) {
    return __fdividef(2.0f, 1.0f + __expf(-2.0f * x)) - 1.0f;
}

// LSTM step: G[32,512] = [A(KA); B(KB)] @ W + bias, then gate update.
// 256-thread collective: unit u = gtid&127 (cols 4u..4u+3),
// batches b0 = (gtid>>7)*16 .. +15. acc[gate][pair] = 32 ull accs.
// Weight LDG prefetch distance 2; activation LDS prefetch distance 1 ->
// the 32 FFMA2 of iter k use registers loaded one iteration earlier.
// Last act prefetch reads 64B past the buffer (into the adjacent smem
// buffer) — safe, values unused.
template <int KA, int KB>
__device__ __forceinline__ void lstm_step(
    const float* __restrict__ W, const float* __restrict__ bias,
    const float* shA, const float* shB, float* shC, float* shOut,
    int u, int b0)
{
    constexpr int K = KA + KB;
    ull acc[4][8];
    {
        float4 bs = *(const float4*)(bias + 4 * u);
        ull d0 = dup2(bs.x), d1 = dup2(bs.y), d2 = dup2(bs.z), d3 = dup2(bs.w);
#pragma unroll
        for (int p = 0; p < 8; ++p) {
            acc[0][p] = d0; acc[1][p] = d1; acc[2][p] = d2; acc[3][p] = d3;
        }
    }
    const float* Wu    = W + 4 * u;
    const float* baseA = shA + b0;
    const float* baseB = shB + b0 - KA * SS;

    float4 w0 = __ldg((const float4*)(Wu));
    float4 w1 = __ldg((const float4*)(Wu + 512));
    // act prefetch for k = 0 (KA >= 1 always)
    ulonglong2 a0 = *(const ulonglong2*)(baseA);
    ulonglong2 a1 = *(const ulonglong2*)(baseA + 4);
    ulonglong2 a2 = *(const ulonglong2*)(baseA + 8);
    ulonglong2 a3 = *(const ulonglong2*)(baseA + 12);

#pragma unroll 4
    for (int k = 0; k < K; ++k) {
        float4 wn = __ldg((const float4*)(Wu + (k + 2) * 512));   // pad-safe
        const float* apn = ((k + 1) < KA ? baseA : baseB) + (k + 1) * SS;
        ulonglong2 n0 = *(const ulonglong2*)(apn);
        ulonglong2 n1 = *(const ulonglong2*)(apn + 4);
        ulonglong2 n2 = *(const ulonglong2*)(apn + 8);
        ulonglong2 n3 = *(const ulonglong2*)(apn + 12);
        ull wd0 = dup2(w0.x), wd1 = dup2(w0.y), wd2 = dup2(w0.z), wd3 = dup2(w0.w);
        fma2(acc[0][0], wd0, a0.x); fma2(acc[0][1], wd0, a0.y);
        fma2(acc[0][2], wd0, a1.x); fma2(acc[0][3], wd0, a1.y);
        fma2(acc[0][4], wd0, a2.x); fma2(acc[0][5], wd0, a2.y);
        fma2(acc[0][6], wd0, a3.x); fma2(acc[0][7], wd0, a3.y);
        fma2(acc[1][0], wd1, a0.x); fma2(acc[1][1], wd1, a0.y);
        fma2(acc[1][2], wd1, a1.x); fma2(acc[1][3], wd1, a1.y);
        fma2(acc[1][4], wd1, a2.x); fma2(acc[1][5], wd1, a2.y);
        fma2(acc[1][6], wd1, a3.x); fma2(acc[1][7], wd1, a3.y);
        fma2(acc[2][0], wd2, a0.x); fma2(acc[2][1], wd2, a0.y);
        fma2(acc[2][2], wd2, a1.x); fma2(acc[2][3], wd2, a1.y);
        fma2(acc[2][4], wd2, a2.x); fma2(acc[2][5], wd2, a2.y);
        fma2(acc[2][6], wd2, a3.x); fma2(acc[2][7], wd2, a3.y);
        fma2(acc[3][0], wd3, a0.x); fma2(acc[3][1], wd3, a0.y);
        fma2(acc[3][2], wd3, a1.x); fma2(acc[3][3], wd3, a1.y);
        fma2(acc[3][4], wd3, a2.x); fma2(acc[3][5], wd3, a2.y);
        fma2(acc[3][6], wd3, a3.x); fma2(acc[3][7], wd3, a3.y);
        w0 = w1; w1 = wn;
        a0 = n0; a1 = n1; a2 = n2; a3 = n3;
    }

    // epilogue: gates -> c update -> s (16 batches)
#pragma unroll
    for (int q = 0; q < 4; ++q) {
        int bq = b0 + 4 * q;
        float gi[4], gf[4], gg[4], go[4];
        unpk(acc[0][2 * q], gi[0], gi[1]); unpk(acc[0][2 * q + 1], gi[2], gi[3]);
        unpk(acc[1][2 * q], gf[0], gf[1]); unpk(acc[1][2 * q + 1], gf[2], gf[3]);
        unpk(acc[2][2 * q], gg[0], gg[1]); unpk(acc[2][2 * q + 1], gg[2], gg[3]);
        unpk(acc[3][2 * q], go[0], go[1]); unpk(acc[3][2 * q + 1], go[2], go[3]);
        float4 cv = *(const float4*)(shC + u * SS + bq);
        float cb[4] = {cv.x, cv.y, cv.z, cv.w};
        float sb[4];
#pragma unroll
        for (int j = 0; j < 4; ++j) {
            float cn = fsig(gf[j]) * cb[j] + fsig(gi[j]) * ftanh(gg[j]);
            cb[j] = cn;
            sb[j] = fsig(go[j]) * ftanh(cn);
        }
        *(float4*)(shC + u * SS + bq)   = make_float4(cb[0], cb[1], cb[2], cb[3]);
        *(float4*)(shOut + u * SS + bq) = make_float4(sb[0], sb[1], sb[2], sb[3]);
    }
}

// hp[32,32] = s[32,128] @ WhrT[128,32], weights dup'd in SMEM (stride 64).
// 256-thread collective: cg = gtid&15 -> cols 2cg,2cg+1;
// p = gtid>>4 -> batches 2p, 2p+1. Pure LDS + FFMA2.
__device__ __forceinline__ void proj_gemm(
    const float* sPW, const float* shS, float* shHdst,
    float* outp, int gtid)
{
    const int cg = gtid & 15;
    const int p  = gtid >> 4;
    ull acc0 = 0ull, acc1 = 0ull;
    const float* Wu = sPW + 4 * cg;
#pragma unroll 8
    for (int k = 0; k < 128; ++k) {
        ulonglong2 w = *(const ulonglong2*)(Wu + k * 64);  // (wc0,wc0),(wc1,wc1)
        ull a = *(const ull*)(shS + k * SS + 2 * p);       // (s_b0, s_b1)
        fma2(acc0, w.x, a);
        fma2(acc1, w.y, a);
    }
    float v00, v10, v01, v11;   // v[b][c]
    unpk(acc0, v00, v10);
    unpk(acc1, v01, v11);
    float* hp = shHdst + (2 * cg) * SS + 2 * p;
    hp[0] = v00; hp[1] = v10;
    hp[SS] = v01; hp[SS + 1] = v11;
    if (outp) {
        *(float2*)(outp + (size_t)(2 * p) * 512 + 2 * cg)     = make_float2(v00, v01);
        *(float2*)(outp + (size_t)(2 * p + 1) * 512 + 2 * cg) = make_float2(v10, v11);
    }
}

// v[8,32] = h_new[32,128] @ WpT[128,8] + bp, weights dup'd in SMEM (stride 16).
// 128 active threads: nn = gtid&7 (one col), p = gtid>>3 (batches 2p,2p+1).
__device__ __forceinline__ void wp_gemm(
    const float* __restrict__ bp, const float* sPWP,
    const float* shS, float* shV, int gtid)
{
    if (gtid >= 128) return;
    const int nn = gtid & 7;
    const int p  = gtid >> 3;
    ull acc = dup2(__ldg(&bp[nn]));
    const float* Wu = sPWP + 2 * nn;
#pragma unroll 8
    for (int k = 0; k < 128; ++k) {
        ull w = *(const ull*)(Wu + k * 16);
        ull a = *(const ull*)(shS + k * SS + 2 * p);
        fma2(acc, w, a);
    }
    float lo, hi;
    unpk(acc, lo, hi);
    shV[nn * SS + 2 * p]     = lo;
    shV[nn * SS + 2 * p + 1] = hi;
}

// quantum measurement physics for one batch element b (0..31); writes xnext
__device__ __forceinline__ void physics(const float* shV, const float* shRHO,
                                        float* shX, int b)
{
    float Mr[2][2][2], Mi[2][2][2];
#pragma unroll
    for (int q = 0; q < 2; ++q) {
        float ar = shV[(q * 4 + 0) * SS + b];
        float ai = shV[(q * 4 + 1) * SS + b];
        float br = shV[(q * 4 + 2) * SS + b];
        float bi = shV[(q * 4 + 3) * SS + b];
        float n00 = ar * ar + ai * ai;
        float n11 = br * br + bi * bi;
        float inv = 1.0f / (n00 + n11);
        float pr = (ar * br + ai * bi) * inv;
        float pi = (ai * br - ar * bi) * inv;
        Mr[q][0][0] = n00 * inv; Mi[q][0][0] = 0.f;
        Mr[q][0][1] = pr;        Mi[q][0][1] = pi;
        Mr[q][1][0] = pr;        Mi[q][1][0] = -pi;
        Mr[q][1][1] = n11 * inv; Mi[q][1][1] = 0.f;
    }
    const float* rp = shRHO + b * 33;
    float m = 0.f;
#pragma unroll
    for (int a = 0; a < 2; ++a)
#pragma unroll
        for (int c = 0; c < 2; ++c)
#pragma unroll
            for (int b2 = 0; b2 < 2; ++b2)
#pragma unroll
                for (int d = 0; d < 2; ++d) {
                    float tr_ = Mr[0][a][c] * Mr[1][b2][d] - Mi[0][a][c] * Mi[1][b2][d];
                    float ti_ = Mr[0][a][c] * Mi[1][b2][d] + Mi[0][a][c] * Mr[1][b2][d];
                    int row = c * 2 + d, col = a * 2 + b2;
                    float rr = rp[row * 4 + col];
                    float ri = rp[16 + row * 4 + col];
                    m += tr_ * rr - ti_ * ri;
                }
    shX[0 * SS + b] = m;
#pragma unroll
    for (int q = 0; q < 2; ++q)
#pragma unroll
        for (int i = 0; i < 2; ++i)
#pragma unroll
            for (int j = 0; j < 2; ++j) {
                int base = 1 + 8 * q + 4 * i + 2 * j;
                shX[base * SS + b]       = Mr[q][i][j];
                shX[(base + 1) * SS + b] = Mi[q][i][j];
            }
}

__global__ void __launch_bounds__(NTH, 1) fused_kernel(
    const float* __restrict__ meas, const float* __restrict__ basis_r,
    const float* __restrict__ basis_i, const float* __restrict__ rho,
    const float* __restrict__ h0in, const float* __restrict__ c0in,
    const float* __restrict__ bp, float* __restrict__ out)
{
    extern __shared__ float sm[];
    float* shS   = sm + OFF_S;
    float* shCC  = sm + OFF_CC;
    float* shH0  = sm + OFF_H0;
    float* shC0  = sm + OFF_C0;
    float* shH1  = sm + OFF_H1;
    float* shC1  = sm + OFF_C1;
    float* shRHO = sm + OFF_RHO;
    float* shV   = sm + OFF_V;
    float* sPW0  = sm + OFF_PW0;
    float* sPW1  = sm + OFF_PW1;
    float* sPWP  = sm + OFF_PWP;

    const int tid = threadIdx.x;
    const int b0g = blockIdx.x * BT;

    // ---- init loads into XA ----
    for (int i = tid; i < BT; i += NTH)
        sm[OFF_XA + 0 * SS + i] = meas[b0g + i];
    for (int i = tid; i < BT * 8; i += NTH) {
        int b = i >> 3, e = i & 7;
        sm[OFF_XA + (1 + 2 * e) * SS + b] = basis_r[(size_t)(b0g + b) * 8 + e];
        sm[OFF_XA + (2 + 2 * e) * SS + b] = basis_i[(size_t)(b0g + b) * 8 + e];
    }
    for (int i = tid; i < BT * 32; i += NTH) {
        int b = i >> 5, e = i & 31;
        shRHO[b * 33 + e] = rho[(size_t)(b0g + b) * 32 + e];
    }
    for (int i = tid; i < BT * 128; i += NTH) {
        int b = i >> 7, u = i & 127;
        sm[OFF_HCA + u * SS + b] = h0in[(size_t)(b0g + b) * 128 + u];
        shCC[u * SS + b]         = c0in[(size_t)(b0g + b) * 128 + u];
    }
    // zero H0, C0, H1, C1 (320 contiguous rows)
    for (int i = tid; i < 320 * SS; i += NTH)
        sm[OFF_H0 + i] = 0.f;
    // fill dup'd small-GEMM weights (once per CTA)
    for (int i = tid; i < 128 * 32; i += NTH) {
        int k = i >> 5, n = i & 31;
        float v0 = __ldg(&g_Whr0T[i]);
        float v1 = __ldg(&g_Whr1T[i]);
        sPW0[k * 64 + 2 * n] = v0; sPW0[k * 64 + 2 * n + 1] = v0;
        sPW1[k * 64 + 2 * n] = v1; sPW1[k * 64 + 2 * n + 1] = v1;
    }
    for (int i = tid; i < 128 * 8; i += NTH) {
        int k = i >> 3, n = i & 7;
        float v = __ldg(&g_WpT[i]);
        sPWP[k * 16 + 2 * n] = v; sPWP[k * 16 + 2 * n + 1] = v;
    }
    __syncthreads();

    const bool isA = (tid < 256);
    const int gtid = tid & 255;
    const int u  = gtid & 127;
    const int b0 = (gtid >> 7) * 16;

    float* xcur = sm + OFF_XA;
    float* xnxt = sm + OFF_XB;
    float* hcur = sm + OFF_HCA;
    float* hnxt = sm + OFF_HCB;

    for (int t = 0; t < 16; ++t) {
        if (isA) {
            // group A: cell chain (produces x_{t+1} into xnxt, h_new into hnxt)
            if (t < 15) {
                lstm_step<17, 128>(g_Wc, g_bc, xcur, hcur, shCC, hnxt, u, b0);
                BARA();
                wp_gemm(bp, sPWP, hnxt, shV, gtid);
                BARA();
                if (gtid < BT) physics(shV, shRHO, xnxt, gtid);
            }
        } else {
            // group B: output chain for step t (reads xcur only)
            lstm_step<17, 32>(g_W0, g_b0, xcur, shH0, shC0, shS, u, b0);
            BARB();
            proj_gemm(sPW0, shS, shH0, nullptr, gtid);
            BARB();
            lstm_step<32, 32>(g_W1, g_b1, shH0, shH1, shC1, shS, u, b0);
            BARB();
            proj_gemm(sPW1, shS, shH1,
                      out + (size_t)b0g * 512 + (size_t)t * 32, gtid);
        }
        __syncthreads();
        if (t < 15) {
            float* tp = hcur; hcur = hnxt; hnxt = tp;
            float* tx = xcur; xcur = xnxt; xnxt = tx;
        }
    }
}

extern "C" void kernel_launch(void* const* d_in, const int* in_sizes, int n_in,
                              void* d_out, int out_size)
{
    const float* meas   = (const float*)d_in[0];
    const float* br     = (const float*)d_in[1];
    const float* bi     = (const float*)d_in[2];
    const float* rho    = (const float*)d_in[3];
    const float* h0     = (const float*)d_in[4];
    const float* c0     = (const float*)d_in[5];
    const float* Wihc   = (const float*)d_in[6];
    const float* Whhc   = (const float*)d_in[7];
    const float* bihc   = (const float*)d_in[8];
    const float* bhhc   = (const float*)d_in[9];
    const float* Wp     = (const float*)d_in[10];
    const float* bp     = (const float*)d_in[11];
    const float* Wih0   = (const float*)d_in[12];
    const float* Whh0   = (const float*)d_in[13];
    const float* bih0   = (const float*)d_in[14];
    const float* bhh0   = (const float*)d_in[15];
    const float* Whr0   = (const float*)d_in[16];
    const float* Wih1   = (const float*)d_in[17];
    const float* Whh1   = (const float*)d_in[18];
    const float* bih1   = (const float*)d_in[19];
    const float* bhh1   = (const float*)d_in[20];
    const float* Whr1   = (const float*)d_in[21];

    int B = in_sizes[0];
    int nblocks = B / BT;

    cudaFuncSetAttribute(fused_kernel,
                         cudaFuncAttributeMaxDynamicSharedMemorySize,
                         SMEM_BYTES);

    prep_kernel<<<128, 256>>>(Wihc, Whhc, bihc, bhhc, Wp,
                              Wih0, Whh0, bih0, bhh0, Whr0,
                              Wih1, Whh1, bih1, bhh1, Whr1);

    fused_kernel<<<nblocks, NTH, SMEM_BYTES>>>(
        meas, br, bi, rho, h0, c0, bp, (float*)d_out);
}

// round 11
// speedup vs baseline: 2.2175x; 1.0321x over previous
#include <cuda_runtime.h>

// ---------------------------------------------------------------------------
// Fused LSTMMeasurementPredictor — round 11
//   B=131072, H=128, NQ=2, P=32, D_IN=17, T=16
// R10 structure (warp-specialized dual chains, act+weight prefetch, pinned
// small-GEMM weights). NEW: lstm_step k-loop split into KA / transition / KB
// segments with pure pointer-bump addressing (no per-iter select/IMAD on the
// prefetch path), unroll 8 on the KB hot loop.
// ---------------------------------------------------------------------------

#define NTH 512
#define BT  32
#define SS  36   // padded row stride; (36*4)%16==0, conflict-free LDS.128

constexpr int OFF_XA  = 0;                   // 17  rows : x ping
constexpr int OFF_XB  = OFF_XA  + 17  * SS;  // 17  rows : x pong
constexpr int OFF_HCA = OFF_XB  + 17  * SS;  // 128 rows : cell h ping
constexpr int OFF_HCB = OFF_HCA + 128 * SS;  // 128 rows : cell h pong
constexpr int OFF_S   = OFF_HCB + 128 * SS;  // 128 rows : group-B s staging
constexpr int OFF_CC  = OFF_S   + 128 * SS;  // 128 rows : cell c
constexpr int OFF_H0  = OFF_CC  + 128 * SS;  // 32  rows : lstm0 proj h
constexpr int OFF_C0  = OFF_H0  + 32  * SS;  // 128 rows : lstm0 c
constexpr int OFF_H1  = OFF_C0  + 128 * SS;  // 32  rows : lstm1 proj h
constexpr int OFF_C1  = OFF_H1  + 32  * SS;  // 128 rows : lstm1 c
constexpr int OFF_RHO = OFF_C1  + 128 * SS;  // 32*33    : rho
constexpr int OFF_V   = OFF_RHO + 32 * 33;   // 8 rows   : projector v
// duplicated-pair small-GEMM weights (filled once per CTA):
constexpr int OFF_PW0 = OFF_V   + 8 * SS;    // 128*64 : Whr0T dup'd
constexpr int OFF_PW1 = OFF_PW0 + 128 * 64;  // 128*64 : Whr1T dup'd
constexpr int OFF_PWP = OFF_PW1 + 128 * 64;  // 128*16 : WpT dup'd
constexpr int SMEM_FLOATS = OFF_PWP + 128 * 16;
constexpr int SMEM_BYTES  = SMEM_FLOATS * 4; // ~199 KB

// compact packed weights: W[k][512], column jp = u*4 + gate (i,f,g,o).
// +1024 floats pad so the distance-2 prefetch can overshoot by 2 rows.
__device__ __align__(16) float g_Wc[145 * 512 + 1024];
__device__ __align__(16) float g_bc[512];
__device__ __align__(16) float g_W0[49 * 512 + 1024];
__device__ __align__(16) float g_b0[512];
__device__ __align__(16) float g_W1[64 * 512 + 1024];
__device__ __align__(16) float g_b1[512];
__device__ __align__(16) float g_Whr0T[128 * 32];   // [k][n] compact
__device__ __align__(16) float g_Whr1T[128 * 32];
__device__ __align__(16) float g_WpT[128 * 8];      // [k][n] compact

__global__ void prep_kernel(
    const float* __restrict__ Wihc, const float* __restrict__ Whhc,
    const float* __restrict__ bihc, const float* __restrict__ bhhc,
    const float* __restrict__ Wp,
    const float* __restrict__ Wih0, const float* __restrict__ Whh0,
    const float* __restrict__ bih0, const float* __restrict__ bhh0,
    const float* __restrict__ Whr0,
    const float* __restrict__ Wih1, const float* __restrict__ Whh1,
    const float* __restrict__ bih1, const float* __restrict__ bhh1,
    const float* __restrict__ Whr1)
{
    int i0 = blockIdx.x * blockDim.x + threadIdx.x;
    int stride = gridDim.x * blockDim.x;

    for (int i = i0; i < 145 * 512; i += stride) {
        int k = i >> 9, jp = i & 511;
        int u = jp >> 2, g = jp & 3, j = g * 128 + u;
        g_Wc[i] = (k < 17) ? Wihc[j * 17 + k] : Whhc[j * 128 + (k - 17)];
    }
    for (int i = i0; i < 49 * 512; i += stride) {
        int k = i >> 9, jp = i & 511;
        int u = jp >> 2, g = jp & 3, j = g * 128 + u;
        g_W0[i] = (k < 17) ? Wih0[j * 17 + k] : Whh0[j * 32 + (k - 17)];
    }
    for (int i = i0; i < 64 * 512; i += stride) {
        int k = i >> 9, jp = i & 511;
        int u = jp >> 2, g = jp & 3, j = g * 128 + u;
        g_W1[i] = (k < 32) ? Wih1[j * 32 + k] : Whh1[j * 32 + (k - 32)];
    }
    for (int i = i0; i < 1024; i += stride) {
        g_Wc[145 * 512 + i] = 0.f;
        g_W0[49 * 512 + i] = 0.f;
        g_W1[64 * 512 + i] = 0.f;
    }
    for (int i = i0; i < 512; i += stride) {
        int u = i >> 2, g = i & 3, j = g * 128 + u;
        g_bc[i] = bihc[j] + bhhc[j];
        g_b0[i] = bih0[j] + bhh0[j];
        g_b1[i] = bih1[j] + bhh1[j];
    }
    for (int i = i0; i < 128 * 32; i += stride) {
        int k = i >> 5, n = i & 31;
        g_Whr0T[i] = Whr0[n * 128 + k];
        g_Whr1T[i] = Whr1[n * 128 + k];
    }
    for (int i = i0; i < 128 * 8; i += stride) {
        int k = i >> 3, n = i & 7;
        g_WpT[i] = Wp[n * 128 + k];
    }
}

// ---------------------------------------------------------------------------
typedef unsigned long long ull;

__device__ __forceinline__ void fma2(ull& acc, ull a, ull b) {
    asm("fma.rn.f32x2 %0, %1, %2, %0;" : "+l"(acc) : "l"(a), "l"(b));
}
__device__ __forceinline__ ull dup2(float x) {
    ull r;
    asm("mov.b64 %0, {%1, %1};" : "=l"(r) : "f"(x));
    return r;
}
__device__ __forceinline__ void unpk(ull v, float& lo, float& hi) {
    asm("mov.b64 {%0, %1}, %2;" : "=f"(lo), "=f"(hi) : "l"(v));
}
#define BARA() asm volatile("bar.sync 1, 256;" ::: "memory")
#define BARB() asm volatile("bar.sync 2, 256;" ::: "memory")

__device__ __forceinline__ float fsig(float x) {
    return __fdividef(1.0f, 1.0f + __expf(-x));
}
__device__ __forceinline__ float ftanh(float x) {
    return __fdividef(2.0f, 1.0f + __expf(-2.0f * x)) - 1.0f;
}

// LSTM step: G[32,512] = [A(KA); B(KB)] @ W + bias, then gate update.
// 256-thread collective: unit u = gtid&127 (cols 4u..4u+3),
// batches b0 = (gtid>>7)*16 .. +15. acc[gate][pair] = 32 ull accs.
// Weight LDG prefetch distance 2 (rolling w0,w1); act LDS prefetch distance 1
// (rolling a0..a3). Loop split KA / transition / KB with pointer bumps —
// no per-iteration select/IMAD on the prefetch address path.
// Final act prefetch reads one row past shB (lands in adjacent buffer; unused).
template <int KA, int KB>
__device__ __forceinline__ void lstm_step(
    const float* __restrict__ W, const float* __restrict__ bias,
    const float* shA, const float* shB, float* shC, float* shOut,
    int u, int b0)
{
    ull acc[4][8];
    {
        float4 bs = *(const float4*)(bias + 4 * u);
        ull d0 = dup2(bs.x), d1 = dup2(bs.y), d2 = dup2(bs.z), d3 = dup2(bs.w);
#pragma unroll
        for (int p = 0; p < 8; ++p) {
            acc[0][p] = d0; acc[1][p] = d1; acc[2][p] = d2; acc[3][p] = d3;
        }
    }
    const float* Wk = W + 4 * u;          // weight ptr for current k
    const float* ap = shA + b0;           // act ptr for current k

    float4 w0 = __ldg((const float4*)(Wk));
    float4 w1 = __ldg((const float4*)(Wk + 512));
    ulonglong2 a0 = *(const ulonglong2*)(ap);
    ulonglong2 a1 = *(const ulonglong2*)(ap + 4);
    ulonglong2 a2 = *(const ulonglong2*)(ap + 8);
    ulonglong2 a3 = *(const ulonglong2*)(ap + 12);

    // one fused-multiply body: prefetch (weights dist-2 via Wk+1024,
    // acts dist-1 from apn), 32 FFMA2 on current regs, roll.
#define LSTM_BODY(APN)                                                        \
    {                                                                         \
        float4 wn = __ldg((const float4*)(Wk + 1024));                        \
        const float* apn_ = (APN);                                            \
        ulonglong2 n0 = *(const ulonglong2*)(apn_);                           \
        ulonglong2 n1 = *(const ulonglong2*)(apn_ + 4);                       \
        ulonglong2 n2 = *(const ulonglong2*)(apn_ + 8);                       \
        ulonglong2 n3 = *(const ulonglong2*)(apn_ + 12);                      \
        ull wd0 = dup2(w0.x), wd1 = dup2(w0.y), wd2 = dup2(w0.z), wd3 = dup2(w0.w); \
        fma2(acc[0][0], wd0, a0.x); fma2(acc[0][1], wd0, a0.y);               \
        fma2(acc[0][2], wd0, a1.x); fma2(acc[0][3], wd0, a1.y);               \
        fma2(acc[0][4], wd0, a2.x); fma2(acc[0][5], wd0, a2.y);               \
        fma2(acc[0][6], wd0, a3.x); fma2(acc[0][7], wd0, a3.y);               \
        fma2(acc[1][0], wd1, a0.x); fma2(acc[1][1], wd1, a0.y);               \
        fma2(acc[1][2], wd1, a1.x); fma2(acc[1][3], wd1, a1.y);               \
        fma2(acc[1][4], wd1, a2.x); fma2(acc[1][5], wd1, a2.y);               \
        fma2(acc[1][6], wd1, a3.x); fma2(acc[1][7], wd1, a3.y);               \
        fma2(acc[2][0], wd2, a0.x); fma2(acc[2][1], wd2, a0.y);               \
        fma2(acc[2][2], wd2, a1.x); fma2(acc[2][3], wd2, a1.y);               \
        fma2(acc[2][4], wd2, a2.x); fma2(acc[2][5], wd2, a2.y);               \
        fma2(acc[2][6], wd2, a3.x); fma2(acc[2][7], wd2, a3.y);               \
        fma2(acc[3][0], wd3, a0.x); fma2(acc[3][1], wd3, a0.y);               \
        fma2(acc[3][2], wd3, a1.x); fma2(acc[3][3], wd3, a1.y);               \
        fma2(acc[3][4], wd3, a2.x); fma2(acc[3][5], wd3, a2.y);               \
        fma2(acc[3][6], wd3, a3.x); fma2(acc[3][7], wd3, a3.y);               \
        w0 = w1; w1 = wn; Wk += 512;                                          \
        a0 = n0; a1 = n1; a2 = n2; a3 = n3;                                   \
    }

    // KA segment (iterations 0..KA-2): next act row is ap+SS
#pragma unroll 4
    for (int k = 0; k < KA - 1; ++k) {
        LSTM_BODY(ap + SS);
        ap += SS;
    }
    // transition iteration (k = KA-1): next act row is shB row 0
    const float* bp_ = shB + b0;
    LSTM_BODY(bp_);
    ap = bp_;
    // KB segment: next act row is ap+SS (last one overshoots 1 row — safe)
#pragma unroll 8
    for (int k = 0; k < KB; ++k) {
        LSTM_BODY(ap + SS);
        ap += SS;
    }
#undef LSTM_BODY

    // epilogue: gates -> c update -> s (16 batches)
#pragma unroll
    for (int q = 0; q < 4; ++q) {
        int bq = b0 + 4 * q;
        float gi[4], gf[4], gg[4], go[4];
        unpk(acc[0][2 * q], gi[0], gi[1]); unpk(acc[0][2 * q + 1], gi[2], gi[3]);
        unpk(acc[1][2 * q], gf[0], gf[1]); unpk(acc[1][2 * q + 1], gf[2], gf[3]);
        unpk(acc[2][2 * q], gg[0], gg[1]); unpk(acc[2][2 * q + 1], gg[2], gg[3]);
        unpk(acc[3][2 * q], go[0], go[1]); unpk(acc[3][2 * q + 1], go[2], go[3]);
        float4 cv = *(const float4*)(shC + u * SS + bq);
        float cb[4] = {cv.x, cv.y, cv.z, cv.w};
        float sb[4];
#pragma unroll
        for (int j = 0; j < 4; ++j) {
            float cn = fsig(gf[j]) * cb[j] + fsig(gi[j]) * ftanh(gg[j]);
            cb[j] = cn;
            sb[j] = fsig(go[j]) * ftanh(cn);
        }
        *(float4*)(shC + u * SS + bq)   = make_float4(cb[0], cb[1], cb[2], cb[3]);
        *(float4*)(shOut + u * SS + bq) = make_float4(sb[0], sb[1], sb[2], sb[3]);
    }
}

// hp[32,32] = s[32,128] @ WhrT[128,32], weights dup'd in SMEM (stride 64).
// 256-thread collective: cg = gtid&15 -> cols 2cg,2cg+1;
// p = gtid>>4 -> batches 2p, 2p+1. Pure LDS + FFMA2.
__device__ __forceinline__ void proj_gemm(
    const float* sPW, const float* shS, float* shHdst,
    float* outp, int gtid)
{
    const int cg = gtid & 15;
    const int p  = gtid >> 4;
    ull acc0 = 0ull, acc1 = 0ull;
    const float* Wu = sPW + 4 * cg;
#pragma unroll 8
    for (int k = 0; k < 128; ++k) {
        ulonglong2 w = *(const ulonglong2*)(Wu + k * 64);  // (wc0,wc0),(wc1,wc1)
        ull a = *(const ull*)(shS + k * SS + 2 * p);       // (s_b0, s_b1)
        fma2(acc0, w.x, a);
        fma2(acc1, w.y, a);
    }
    float v00, v10, v01, v11;   // v[b][c]
    unpk(acc0, v00, v10);
    unpk(acc1, v01, v11);
    float* hp = shHdst + (2 * cg) * SS + 2 * p;
    hp[0] = v00; hp[1] = v10;
    hp[SS] = v01; hp[SS + 1] = v11;
    if (outp) {
        *(float2*)(outp + (size_t)(2 * p) * 512 + 2 * cg)     = make_float2(v00, v01);
        *(float2*)(outp + (size_t)(2 * p + 1) * 512 + 2 * cg) = make_float2(v10, v11);
    }
}

// v[8,32] = h_new[32,128] @ WpT[128,8] + bp, weights dup'd in SMEM (stride 16).
// 128 active threads: nn = gtid&7 (one col), p = gtid>>3 (batches 2p,2p+1).
__device__ __forceinline__ void wp_gemm(
    const float* __restrict__ bp, const float* sPWP,
    const float* shS, float* shV, int gtid)
{
    if (gtid >= 128) return;
    const int nn = gtid & 7;
    const int p  = gtid >> 3;
    ull acc = dup2(__ldg(&bp[nn]));
    const float* Wu = sPWP + 2 * nn;
#pragma unroll 8
    for (int k = 0; k < 128; ++k) {
        ull w = *(const ull*)(Wu + k * 16);
        ull a = *(const ull*)(shS + k * SS + 2 * p);
        fma2(acc, w, a);
    }
    float lo, hi;
    unpk(acc, lo, hi);
    shV[nn * SS + 2 * p]     = lo;
    shV[nn * SS + 2 * p + 1] = hi;
}

// quantum measurement physics for one batch element b (0..31); writes xnext
__device__ __forceinline__ void physics(const float* shV, const float* shRHO,
                                        float* shX, int b)
{
    float Mr[2][2][2], Mi[2][2][2];
#pragma unroll
    for (int q = 0; q < 2; ++q) {
        float ar = shV[(q * 4 + 0) * SS + b];
        float ai = shV[(q * 4 + 1) * SS + b];
        float br = shV[(q * 4 + 2) * SS + b];
        float bi = shV[(q * 4 + 3) * SS + b];
        float n00 = ar * ar + ai * ai;
        float n11 = br * br + bi * bi;
        float inv = 1.0f / (n00 + n11);
        float pr = (ar * br + ai * bi) * inv;
        float pi = (ai * br - ar * bi) * inv;
        Mr[q][0][0] = n00 * inv; Mi[q][0][0] = 0.f;
        Mr[q][0][1] = pr;        Mi[q][0][1] = pi;
        Mr[q][1][0] = pr;        Mi[q][1][0] = -pi;
        Mr[q][1][1] = n11 * inv; Mi[q][1][1] = 0.f;
    }
    const float* rp = shRHO + b * 33;
    float m = 0.f;
#pragma unroll
    for (int a = 0; a < 2; ++a)
#pragma unroll
        for (int c = 0; c < 2; ++c)
#pragma unroll
            for (int b2 = 0; b2 < 2; ++b2)
#pragma unroll
                for (int d = 0; d < 2; ++d) {
                    float tr_ = Mr[0][a][c] * Mr[1][b2][d] - Mi[0][a][c] * Mi[1][b2][d];
                    float ti_ = Mr[0][a][c] * Mi[1][b2][d] + Mi[0][a][c] * Mr[1][b2][d];
                    int row = c * 2 + d, col = a * 2 + b2;
                    float rr = rp[row * 4 + col];
                    float ri = rp[16 + row * 4 + col];
                    m += tr_ * rr - ti_ * ri;
                }
    shX[0 * SS + b] = m;
#pragma unroll
    for (int q = 0; q < 2; ++q)
#pragma unroll
        for (int i = 0; i < 2; ++i)
#pragma unroll
            for (int j = 0; j < 2; ++j) {
                int base = 1 + 8 * q + 4 * i + 2 * j;
                shX[base * SS + b]       = Mr[q][i][j];
                shX[(base + 1) * SS + b] = Mi[q][i][j];
            }
}

__global__ void __launch_bounds__(NTH, 1) fused_kernel(
    const float* __restrict__ meas, const float* __restrict__ basis_r,
    const float* __restrict__ basis_i, const float* __restrict__ rho,
    const float* __restrict__ h0in, const float* __restrict__ c0in,
    const float* __restrict__ bp, float* __restrict__ out)
{
    extern __shared__ float sm[];
    float* shS   = sm + OFF_S;
    float* shCC  = sm + OFF_CC;
    float* shH0  = sm + OFF_H0;
    float* shC0  = sm + OFF_C0;
    float* shH1  = sm + OFF_H1;
    float* shC1  = sm + OFF_C1;
    float* shRHO = sm + OFF_RHO;
    float* shV   = sm + OFF_V;
    float* sPW0  = sm + OFF_PW0;
    float* sPW1  = sm + OFF_PW1;
    float* sPWP  = sm + OFF_PWP;

    const int tid = threadIdx.x;
    const int b0g = blockIdx.x * BT;

    // ---- init loads into XA ----
    for (int i = tid; i < BT; i += NTH)
        sm[OFF_XA + 0 * SS + i] = meas[b0g + i];
    for (int i = tid; i < BT * 8; i += NTH) {
        int b = i >> 3, e = i & 7;
        sm[OFF_XA + (1 + 2 * e) * SS + b] = basis_r[(size_t)(b0g + b) * 8 + e];
        sm[OFF_XA + (2 + 2 * e) * SS + b] = basis_i[(size_t)(b0g + b) * 8 + e];
    }
    for (int i = tid; i < BT * 32; i += NTH) {
        int b = i >> 5, e = i & 31;
        shRHO[b * 33 + e] = rho[(size_t)(b0g + b) * 32 + e];
    }
    for (int i = tid; i < BT * 128; i += NTH) {
        int b = i >> 7, u = i & 127;
        sm[OFF_HCA + u * SS + b] = h0in[(size_t)(b0g + b) * 128 + u];
        shCC[u * SS + b]         = c0in[(size_t)(b0g + b) * 128 + u];
    }
    // zero H0, C0, H1, C1 (320 contiguous rows)
    for (int i = tid; i < 320 * SS; i += NTH)
        sm[OFF_H0 + i] = 0.f;
    // fill dup'd small-GEMM weights (once per CTA)
    for (int i = tid; i < 128 * 32; i += NTH) {
        int k = i >> 5, n = i & 31;
        float v0 = __ldg(&g_Whr0T[i]);
        float v1 = __ldg(&g_Whr1T[i]);
        sPW0[k * 64 + 2 * n] = v0; sPW0[k * 64 + 2 * n + 1] = v0;
        sPW1[k * 64 + 2 * n] = v1; sPW1[k * 64 + 2 * n + 1] = v1;
    }
    for (int i = tid; i < 128 * 8; i += NTH) {
        int k = i >> 3, n = i & 7;
        float v = __ldg(&g_WpT[i]);
        sPWP[k * 16 + 2 * n] = v; sPWP[k * 16 + 2 * n + 1] = v;
    }
    __syncthreads();

    const bool isA = (tid < 256);
    const int gtid = tid & 255;
    const int u  = gtid & 127;
    const int b0 = (gtid >> 7) * 16;

    float* xcur = sm + OFF_XA;
    float* xnxt = sm + OFF_XB;
    float* hcur = sm + OFF_HCA;
    float* hnxt = sm + OFF_HCB;

    for (int t = 0; t < 16; ++t) {
        if (isA) {
            // group A: cell chain (produces x_{t+1} into xnxt, h_new into hnxt)
            if (t < 15) {
                lstm_step<17, 128>(g_Wc, g_bc, xcur, hcur, shCC, hnxt, u, b0);
                BARA();
                wp_gemm(bp, sPWP, hnxt, shV, gtid);
                BARA();
                if (gtid < BT) physics(shV, shRHO, xnxt, gtid);
            }
        } else {
            // group B: output chain for step t (reads xcur only)
            lstm_step<17, 32>(g_W0, g_b0, xcur, shH0, shC0, shS, u, b0);
            BARB();
            proj_gemm(sPW0, shS, shH0, nullptr, gtid);
            BARB();
            lstm_step<32, 32>(g_W1, g_b1, shH0, shH1, shC1, shS, u, b0);
            BARB();
            proj_gemm(sPW1, shS, shH1,
                      out + (size_t)b0g * 512 + (size_t)t * 32, gtid);
        }
        __syncthreads();
        if (t < 15) {
            float* tp = hcur; hcur = hnxt; hnxt = tp;
            float* tx = xcur; xcur = xnxt; xnxt = tx;
        }
    }
}

extern "C" void kernel_launch(void* const* d_in, const int* in_sizes, int n_in,
                              void* d_out, int out_size)
{
    const float* meas   = (const float*)d_in[0];
    const float* br     = (const float*)d_in[1];
    const float* bi     = (const float*)d_in[2];
    const float* rho    = (const float*)d_in[3];
    const float* h0     = (const float*)d_in[4];
    const float* c0     = (const float*)d_in[5];
    const float* Wihc   = (const float*)d_in[6];
    const float* Whhc   = (const float*)d_in[7];
    const float* bihc   = (const float*)d_in[8];
    const float* bhhc   = (const float*)d_in[9];
    const float* Wp     = (const float*)d_in[10];
    const float* bp     = (const float*)d_in[11];
    const float* Wih0   = (const float*)d_in[12];
    const float* Whh0   = (const float*)d_in[13];
    const float* bih0   = (const float*)d_in[14];
    const float* bhh0   = (const float*)d_in[15];
    const float* Whr0   = (const float*)d_in[16];
    const float* Wih1   = (const float*)d_in[17];
    const float* Whh1   = (const float*)d_in[18];
    const float* bih1   = (const float*)d_in[19];
    const float* bhh1   = (const float*)d_in[20];
    const float* Whr1   = (const float*)d_in[21];

    int B = in_sizes[0];
    int nblocks = B / BT;

    cudaFuncSetAttribute(fused_kernel,
                         cudaFuncAttributeMaxDynamicSharedMemorySize,
                         SMEM_BYTES);

    prep_kernel<<<128, 256>>>(Wihc, Whhc, bihc, bhhc, Wp,
                              Wih0, Whh0, bih0, bhh0, Whr0,
                              Wih1, Whh1, bih1, bhh1, Whr1);

    fused_kernel<<<nblocks, NTH, SMEM_BYTES>>>(
        meas, br, bi, rho, h0, c0, bp, (float*)d_out);
}